// round 6
// baseline (speedup 1.0000x reference)
#include <cuda_runtime.h>
#include <math.h>

#define Nn 4
#define Cc 512
#define Ll 4096
#define Dd 256
#define Kk 8192
#define Pp (Nn*Ll)               // 16384 positions
#define OUT_Y ((size_t)Nn*Cc*Ll) // 8388608
#define OUT_LOSS (OUT_Y + Pp)    // 8404992

typedef unsigned long long u64;

// packed fp32x2 FMA (sm_103a): 2 IEEE fp32 FMAs per instruction, bit-exact
#define FMA2(d, a, b, c) \
    asm("fma.rn.f32x2 %0, %1, %2, %3;" : "=l"(d) : "l"(a), "l"(b), "l"(c))
#define DUP2(d, s) \
    asm("mov.b64 %0, {%1, %1};" : "=l"(d) : "f"(s))

__device__ __forceinline__ float lo32f(u64 v) { return __uint_as_float((unsigned)(v & 0xffffffffu)); }
__device__ __forceinline__ float hi32f(u64 v) { return __uint_as_float((unsigned)(v >> 32)); }

// smem column swizzle for 128-wide transposed tiles: 4-float gap every 32
#define SWZ(c) ((c) + (((c) >> 5) << 2))
#define SST 144   // swizzled row stride in floats (>=139, 16B-multiple)

// -------- device scratch (static, no allocation) --------
__device__ float g_Win[Dd*Cc];           // 512 KB
__device__ float g_Wout[Cc*Dd];          // 512 KB
__device__ float g_Wq[(size_t)Kk*Cc];    // 16 MB  (codebook @ W_out^T)
__device__ float g_invn[Kk];             // 1/max(||cb_k||, eps)
__device__ float g_zet[(size_t)Pp*Dd];   // 16 MB  z_e transposed: [pos][d]
__device__ int   g_idx[Pp];
__device__ float g_losspart[Pp/64];      // per-search-block partial loss

// ---- 8x8 microtile step: 8 a-scalars (dup'd) x 4 b-pairs -> 32 FFMA2 ----
#define ROW4(acc, i, av, B0, B1) do { u64 ad_; DUP2(ad_, av);                     \
    FMA2(acc[i][0], ad_, B0.x, acc[i][0]); FMA2(acc[i][1], ad_, B0.y, acc[i][1]); \
    FMA2(acc[i][2], ad_, B1.x, acc[i][2]); FMA2(acc[i][3], ad_, B1.y, acc[i][3]); } while (0)

#define DSTEP(acc, arow, bptr) do {                                 \
    float4 A0 = *(const float4*)&(arow)[ty*8];                      \
    float4 A1 = *(const float4*)&(arow)[ty*8 + 4];                  \
    ulonglong2 B0 = *(const ulonglong2*)(bptr);                     \
    ulonglong2 B1 = *(const ulonglong2*)((bptr) + 4);               \
    ROW4(acc, 0, A0.x, B0, B1); ROW4(acc, 1, A0.y, B0, B1);         \
    ROW4(acc, 2, A0.z, B0, B1); ROW4(acc, 3, A0.w, B0, B1);         \
    ROW4(acc, 4, A1.x, B0, B1); ROW4(acc, 5, A1.y, B0, B1);         \
    ROW4(acc, 6, A1.z, B0, B1); ROW4(acc, 7, A1.w, B0, B1); } while (0)

// ================= prep: weight_norm rows =================
__global__ void __launch_bounds__(128) prep_wn_kernel(
    const float* __restrict__ v, const float* __restrict__ g, int cols, int sel)
{
    float* W = sel ? g_Wout : g_Win;
    const int r = blockIdx.x, tid = threadIdx.x;
    float s = 0.f;
    for (int c = tid; c < cols; c += 128) { float t = v[(size_t)r*cols + c]; s = fmaf(t, t, s); }
    #pragma unroll
    for (int m = 16; m; m >>= 1) s += __shfl_xor_sync(0xffffffffu, s, m);
    __shared__ float red[4];
    if ((tid & 31) == 0) red[tid >> 5] = s;
    __syncthreads();
    s = red[0] + red[1] + red[2] + red[3];
    const float scale = g[r] / sqrtf(s);
    for (int c = tid; c < cols; c += 128)
        W[(size_t)r*cols + c] = v[(size_t)r*cols + c] * scale;
}

// ================= prep: codebook inverse norms =================
__global__ void __launch_bounds__(128) prep_cbinv_kernel(const float* __restrict__ cb)
{
    const int r = blockIdx.x, tid = threadIdx.x;
    float s = 0.f;
    for (int c = tid; c < Dd; c += 128) { float t = cb[(size_t)r*Dd + c]; s = fmaf(t, t, s); }
    #pragma unroll
    for (int m = 16; m; m >>= 1) s += __shfl_xor_sync(0xffffffffu, s, m);
    __shared__ float red[4];
    if ((tid & 31) == 0) red[tid >> 5] = s;
    __syncthreads();
    if (tid == 0) {
        s = red[0] + red[1] + red[2] + red[3];
        g_invn[r] = 1.f / fmaxf(sqrtf(s), 1e-8f);
    }
}

// ================= z_e GEMM: 64l x 128d tile, K over C=512 =================
// zet[n*L+l][d] = sum_c Win[d][c]*x[n][c][l] + in_b[d]
__global__ void __launch_bounds__(128) ze_gemm_kernel(
    const float* __restrict__ x, const float* __restrict__ inb)
{
    extern __shared__ float dynsm[];
    float (*xs)[32][64]  = (float(*)[32][64])dynsm;             // [2][c'][l']
    float (*ws)[32][SST] = (float(*)[32][SST])(dynsm + 2*32*64);// [2][c'][d'-swz]
    const int tid = threadIdx.x, ty = tid >> 4, tx = tid & 15;
    const int t15 = tid & 15, thi = tid >> 4;
    const int l0 = blockIdx.x * 64, d0 = blockIdx.y * 128, n = blockIdx.z;
    const float* xn = x + (size_t)n * Cc * Ll;
    const int boff = SWZ(tx*8);

    u64 acc[8][4];
    #pragma unroll
    for (int i = 0; i < 8; i++)
        #pragma unroll
        for (int j = 0; j < 4; j++) acc[i][j] = 0ull;

    float4 px[4], pw[8];
    // prefetch + commit chunk 0
    #pragma unroll
    for (int it = 0; it < 4; it++)
        px[it] = *(const float4*)&xn[(size_t)(thi + 8*it)*Ll + l0 + t15*4];
    #pragma unroll
    for (int it = 0; it < 8; it++)
        pw[it] = *(const float4*)&g_Win[(size_t)(d0 + t15 + 16*it)*Cc + thi*4];
    #pragma unroll
    for (int it = 0; it < 4; it++)
        *(float4*)&xs[0][thi + 8*it][t15*4] = px[it];
    #pragma unroll
    for (int it = 0; it < 8; it++) {
        float* dst = &ws[0][thi*4][SWZ(t15 + 16*it)];
        dst[0] = pw[it].x; dst[SST] = pw[it].y; dst[2*SST] = pw[it].z; dst[3*SST] = pw[it].w;
    }
    __syncthreads();

    for (int cs = 0; cs < 16; cs++) {
        const int cur = cs & 1;
        if (cs + 1 < 16) {
            const int cn = (cs + 1) * 32;
            #pragma unroll
            for (int it = 0; it < 4; it++)
                px[it] = *(const float4*)&xn[(size_t)(cn + thi + 8*it)*Ll + l0 + t15*4];
            #pragma unroll
            for (int it = 0; it < 8; it++)
                pw[it] = *(const float4*)&g_Win[(size_t)(d0 + t15 + 16*it)*Cc + cn + thi*4];
        }
        #pragma unroll 8
        for (int d = 0; d < 32; d++)
            DSTEP(acc, xs[cur][d], &ws[cur][d][boff]);
        if (cs + 1 < 16) {
            #pragma unroll
            for (int it = 0; it < 4; it++)
                *(float4*)&xs[cur ^ 1][thi + 8*it][t15*4] = px[it];
            #pragma unroll
            for (int it = 0; it < 8; it++) {
                float* dst = &ws[cur ^ 1][thi*4][SWZ(t15 + 16*it)];
                dst[0] = pw[it].x; dst[SST] = pw[it].y; dst[2*SST] = pw[it].z; dst[3*SST] = pw[it].w;
            }
        }
        __syncthreads();
    }

    float4 bv0 = *(const float4*)&inb[d0 + tx*8];
    float4 bv1 = *(const float4*)&inb[d0 + tx*8 + 4];
    #pragma unroll
    for (int i = 0; i < 8; i++) {
        const int l = l0 + ty*8 + i;
        float* op = &g_zet[((size_t)(n*Ll + l))*Dd + d0 + tx*8];
        float4 o0, o1;
        o0.x = lo32f(acc[i][0]) + bv0.x;  o0.y = hi32f(acc[i][0]) + bv0.y;
        o0.z = lo32f(acc[i][1]) + bv0.z;  o0.w = hi32f(acc[i][1]) + bv0.w;
        o1.x = lo32f(acc[i][2]) + bv1.x;  o1.y = hi32f(acc[i][2]) + bv1.y;
        o1.z = lo32f(acc[i][3]) + bv1.z;  o1.w = hi32f(acc[i][3]) + bv1.w;
        *(float4*)op = o0; *(float4*)(op + 4) = o1;
    }
}

// ================= Wq GEMM: 64k x 128c tile, K over D=256 =================
// Wq[k][c] = sum_d cb[k][d]*Wout[c][d]
__global__ void __launch_bounds__(128) wq_gemm_kernel(const float* __restrict__ cb)
{
    extern __shared__ float dynsm[];
    float (*as_)[32][64]  = (float(*)[32][64])dynsm;              // [2][d'][k']
    float (*bs_)[32][SST] = (float(*)[32][SST])(dynsm + 2*32*64); // [2][d'][c'-swz]
    const int tid = threadIdx.x, ty = tid >> 4, tx = tid & 15;
    const int t15 = tid & 15, thi = tid >> 4;
    const int k0 = blockIdx.x * 64, c0 = blockIdx.y * 128;
    const int boff = SWZ(tx*8);

    u64 acc[8][4];
    #pragma unroll
    for (int i = 0; i < 8; i++)
        #pragma unroll
        for (int j = 0; j < 4; j++) acc[i][j] = 0ull;

    float4 pa[4], pb[8];
    #pragma unroll
    for (int it = 0; it < 4; it++)
        pa[it] = *(const float4*)&cb[(size_t)(k0 + t15 + 16*it)*Dd + thi*4];
    #pragma unroll
    for (int it = 0; it < 8; it++)
        pb[it] = *(const float4*)&g_Wout[(size_t)(c0 + t15 + 16*it)*Dd + thi*4];
    #pragma unroll
    for (int it = 0; it < 4; it++) {
        float* dst = &as_[0][thi*4][t15 + 16*it];
        dst[0] = pa[it].x; dst[64] = pa[it].y; dst[128] = pa[it].z; dst[192] = pa[it].w;
    }
    #pragma unroll
    for (int it = 0; it < 8; it++) {
        float* dst = &bs_[0][thi*4][SWZ(t15 + 16*it)];
        dst[0] = pb[it].x; dst[SST] = pb[it].y; dst[2*SST] = pb[it].z; dst[3*SST] = pb[it].w;
    }
    __syncthreads();

    for (int cs = 0; cs < 8; cs++) {
        const int cur = cs & 1;
        if (cs + 1 < 8) {
            const int dn = (cs + 1) * 32;
            #pragma unroll
            for (int it = 0; it < 4; it++)
                pa[it] = *(const float4*)&cb[(size_t)(k0 + t15 + 16*it)*Dd + dn + thi*4];
            #pragma unroll
            for (int it = 0; it < 8; it++)
                pb[it] = *(const float4*)&g_Wout[(size_t)(c0 + t15 + 16*it)*Dd + dn + thi*4];
        }
        #pragma unroll 8
        for (int d = 0; d < 32; d++)
            DSTEP(acc, as_[cur][d], &bs_[cur][d][boff]);
        if (cs + 1 < 8) {
            #pragma unroll
            for (int it = 0; it < 4; it++) {
                float* dst = &as_[cur ^ 1][thi*4][t15 + 16*it];
                dst[0] = pa[it].x; dst[64] = pa[it].y; dst[128] = pa[it].z; dst[192] = pa[it].w;
            }
            #pragma unroll
            for (int it = 0; it < 8; it++) {
                float* dst = &bs_[cur ^ 1][thi*4][SWZ(t15 + 16*it)];
                dst[0] = pb[it].x; dst[SST] = pb[it].y; dst[2*SST] = pb[it].z; dst[3*SST] = pb[it].w;
            }
        }
        __syncthreads();
    }

    #pragma unroll
    for (int i = 0; i < 8; i++) {
        const int k = k0 + ty*8 + i;
        float* op = &g_Wq[(size_t)k*Cc + c0 + tx*8];
        float4 o0, o1;
        o0.x = lo32f(acc[i][0]); o0.y = hi32f(acc[i][0]);
        o0.z = lo32f(acc[i][1]); o0.w = hi32f(acc[i][1]);
        o1.x = lo32f(acc[i][2]); o1.y = hi32f(acc[i][2]);
        o1.z = lo32f(acc[i][3]); o1.w = hi32f(acc[i][3]);
        *(float4*)op = o0; *(float4*)(op + 4) = o1;
    }
}

// ================= fused search: 64 pos x 128-code chunks, 8x8 microtile =================
__global__ void __launch_bounds__(128) search_kernel(
    const float* __restrict__ cb, float* __restrict__ out)
{
    extern __shared__ float dynsm[];
    float (*ze)[64] = (float(*)[64])dynsm;               // [256 d][64 pos]
    float* cbsA = dynsm + 256*64;                        // [32][SST]
    float* cbsB = cbsA + 32*SST;
    __shared__ int   sidx[64];
    __shared__ float lred[4];

    const int tid = threadIdx.x, ty = tid >> 4, tx = tid & 15;
    const int t15 = tid & 15, thi = tid >> 4;
    const int p0 = blockIdx.x * 64;
    const int boff = SWZ(tx*8);

    // load ze tile transposed (conflict-free STS: quads write consecutive pos)
    #pragma unroll 4
    for (int it = 0; it < 32; it++) {
        int flat = it*128 + tid;
        int d4 = flat >> 6, pos = flat & 63;
        float4 v = *(const float4*)&g_zet[(size_t)(p0 + pos)*Dd + d4*4];
        ze[d4*4 + 0][pos] = v.x; ze[d4*4 + 1][pos] = v.y;
        ze[d4*4 + 2][pos] = v.z; ze[d4*4 + 3][pos] = v.w;
    }

    float4 pre[8];
    // prefetch + commit chunk 0 (k0=0, dt=0)
    #pragma unroll
    for (int it = 0; it < 8; it++)
        pre[it] = *(const float4*)&cb[(size_t)(t15 + 16*it)*Dd + thi*4];
    #pragma unroll
    for (int it = 0; it < 8; it++) {
        float* dst = &cbsA[(thi*4)*SST + SWZ(t15 + 16*it)];
        dst[0] = pre[it].x; dst[SST] = pre[it].y; dst[2*SST] = pre[it].z; dst[3*SST] = pre[it].w;
    }
    __syncthreads();

    float best[8]; int bidx[8];
    #pragma unroll
    for (int i = 0; i < 8; i++) { best[i] = -3.4e38f; bidx[i] = 0; }

    u64 acc[8][4];
    #pragma unroll
    for (int i = 0; i < 8; i++)
        #pragma unroll
        for (int j = 0; j < 4; j++) acc[i][j] = 0ull;

    for (int cs = 0; cs < 512; cs++) {
        float* buf  = (cs & 1) ? cbsB : cbsA;
        float* nbuf = (cs & 1) ? cbsA : cbsB;
        if (cs + 1 < 512) {
            const int nk = ((cs + 1) >> 3) * 128;
            const int ndt = ((cs + 1) & 7) * 32;
            #pragma unroll
            for (int it = 0; it < 8; it++)
                pre[it] = *(const float4*)&cb[(size_t)(nk + t15 + 16*it)*Dd + ndt + thi*4];
        }
        const float (*zef)[64] = ze + (cs & 7)*32;
        #pragma unroll 8
        for (int d = 0; d < 32; d++)
            DSTEP(acc, zef[d], &buf[d*SST + boff]);
        if (cs + 1 < 512) {
            #pragma unroll
            for (int it = 0; it < 8; it++) {
                float* dst = &nbuf[(thi*4)*SST + SWZ(t15 + 16*it)];
                dst[0] = pre[it].x; dst[SST] = pre[it].y; dst[2*SST] = pre[it].z; dst[3*SST] = pre[it].w;
            }
        }
        __syncthreads();
        if ((cs & 7) == 7) {
            const int k0 = (cs >> 3) * 128;
            float4 iv0 = *(const float4*)&g_invn[k0 + tx*8];
            float4 iv1 = *(const float4*)&g_invn[k0 + tx*8 + 4];
            const float ivs[8] = {iv0.x, iv0.y, iv0.z, iv0.w, iv1.x, iv1.y, iv1.z, iv1.w};
            #pragma unroll
            for (int j = 0; j < 4; j++) {
                const int k = k0 + tx*8 + j*2;
                #pragma unroll
                for (int i = 0; i < 8; i++) {
                    float vlo = lo32f(acc[i][j]) * ivs[j*2];
                    float vhi = hi32f(acc[i][j]) * ivs[j*2 + 1];
                    if (vlo > best[i]) { best[i] = vlo; bidx[i] = k; }
                    if (vhi > best[i]) { best[i] = vhi; bidx[i] = k + 1; }
                    acc[i][j] = 0ull;
                }
            }
        }
    }

    // reduce over the 16 code-lanes sharing each position group (ties -> lowest k)
    #pragma unroll
    for (int i = 0; i < 8; i++) {
        float b = best[i]; int ix = bidx[i];
        #pragma unroll
        for (int m = 1; m < 16; m <<= 1) {
            float ob = __shfl_xor_sync(0xffffffffu, b, m);
            int   oi = __shfl_xor_sync(0xffffffffu, ix, m);
            if (ob > b || (ob == b && oi < ix)) { b = ob; ix = oi; }
        }
        if (tx == 0) {
            int pos = ty*8 + i;
            sidx[pos] = ix;
            g_idx[p0 + pos] = ix;
            out[OUT_Y + p0 + pos] = (float)ix;
        }
    }
    __syncthreads();

    // fused VQ loss: sum over (pos,d) of (cb[idx] - z_e)^2
    float ls = 0.f;
    for (int i = tid; i < 64*256; i += 128) {
        int pos = i >> 8, d = i & 255;
        float diff = cb[(size_t)sidx[pos]*Dd + d] - ze[d][pos];
        ls = fmaf(diff, diff, ls);
    }
    #pragma unroll
    for (int m = 16; m; m >>= 1) ls += __shfl_xor_sync(0xffffffffu, ls, m);
    if ((tid & 31) == 0) lred[tid >> 5] = ls;
    __syncthreads();
    if (tid == 0) g_losspart[blockIdx.x] = lred[0] + lred[1] + lred[2] + lred[3];
}

// ================= y gather: y[n][c][l] = Wq[idx[n,l]][c] + out_b[c] =================
__global__ void __launch_bounds__(256) gather_kernel(
    const float* __restrict__ outb, float* __restrict__ out)
{
    extern __shared__ float sm[];   // [32][513]
    __shared__ int sidx[32];
    const int tid = threadIdx.x;
    const int l0 = blockIdx.x * 32, n = blockIdx.y;
    if (tid < 32) sidx[tid] = g_idx[n*Ll + l0 + tid];
    __syncthreads();
    for (int i = tid; i < 32*512; i += 256) {
        int l = i >> 9, c = i & 511;
        sm[l*513 + c] = g_Wq[(size_t)sidx[l]*Cc + c];
    }
    __syncthreads();
    for (int i = tid; i < 512*32; i += 256) {
        int c = i >> 5, l = i & 31;
        out[((size_t)n*Cc + c)*Ll + l0 + l] = sm[l*513 + c] + __ldg(&outb[c]);
    }
}

// ================= finalize losses =================
__global__ void finalize_kernel(float* __restrict__ out)
{
    const int tid = threadIdx.x;            // 128 threads: 4 warps, one per n
    const int n = tid >> 5, lane = tid & 31;
    float s = g_losspart[n*64 + lane] + g_losspart[n*64 + 32 + lane];
    #pragma unroll
    for (int m = 16; m; m >>= 1) s += __shfl_xor_sync(0xffffffffu, s, m);
    if (lane == 0) {
        float v = s * (1.0f / (float)(Dd * Ll));
        out[OUT_LOSS + n]     = v;   // cb_loss
        out[OUT_LOSS + 4 + n] = v;   // cm_loss (numerically identical)
    }
}

// ================= launch =================
extern "C" void kernel_launch(void* const* d_in, const int* in_sizes, int n_in,
                              void* d_out, int out_size)
{
    (void)in_sizes; (void)n_in; (void)out_size;
    const float* x    = (const float*)d_in[0];
    const float* vin  = (const float*)d_in[1];
    const float* gin  = (const float*)d_in[2];
    const float* bin  = (const float*)d_in[3];
    const float* vout = (const float*)d_in[4];
    const float* gout = (const float*)d_in[5];
    const float* bout = (const float*)d_in[6];
    const float* cb   = (const float*)d_in[7];
    float* out = (float*)d_out;

    const int SEARCH_SMEM = (256*64 + 2*32*SST) * 4;     // 102400 B
    const int GEMM_SMEM   = (2*32*64 + 2*32*SST) * 4;    // 53248 B
    const int GATHER_SMEM = 32*513*4;                    // 65664 B
    cudaFuncSetAttribute(search_kernel,  cudaFuncAttributeMaxDynamicSharedMemorySize, SEARCH_SMEM);
    cudaFuncSetAttribute(ze_gemm_kernel, cudaFuncAttributeMaxDynamicSharedMemorySize, GEMM_SMEM);
    cudaFuncSetAttribute(wq_gemm_kernel, cudaFuncAttributeMaxDynamicSharedMemorySize, GEMM_SMEM);
    cudaFuncSetAttribute(gather_kernel,  cudaFuncAttributeMaxDynamicSharedMemorySize, GATHER_SMEM);

    prep_wn_kernel<<<Dd, 128>>>(vin, gin, Cc, 0);
    prep_wn_kernel<<<Cc, 128>>>(vout, gout, Dd, 1);
    prep_cbinv_kernel<<<Kk, 128>>>(cb);
    ze_gemm_kernel<<<dim3(Ll/64, Dd/128, Nn), 128, GEMM_SMEM>>>(x, bin);
    wq_gemm_kernel<<<dim3(Kk/64, Cc/128), 128, GEMM_SMEM>>>(cb);
    search_kernel<<<Pp/64, 128, SEARCH_SMEM>>>(cb, out);
    gather_kernel<<<dim3(Ll/32, Nn), 256, GATHER_SMEM>>>(bout, out);
    finalize_kernel<<<1, 128>>>(out);
}

// round 7
// speedup vs baseline: 1.1694x; 1.1694x over previous
#include <cuda_runtime.h>
#include <math.h>

#define Nn 4
#define Cc 512
#define Ll 4096
#define Dd 256
#define Kk 8192
#define Pp (Nn*Ll)               // 16384 positions
#define OUT_Y ((size_t)Nn*Cc*Ll) // 8388608
#define OUT_LOSS (OUT_Y + Pp)    // 8404992

typedef unsigned long long u64;

// packed fp32x2 FMA (sm_103a): 2 IEEE fp32 FMAs per instruction, bit-exact
#define FMA2(d, a, b, c) \
    asm("fma.rn.f32x2 %0, %1, %2, %3;" : "=l"(d) : "l"(a), "l"(b), "l"(c))
#define DUP2(d, s) \
    asm("mov.b64 %0, {%1, %1};" : "=l"(d) : "f"(s))

__device__ __forceinline__ float lo32f(u64 v) { return __uint_as_float((unsigned)(v & 0xffffffffu)); }
__device__ __forceinline__ float hi32f(u64 v) { return __uint_as_float((unsigned)(v >> 32)); }

// -------- device scratch (static, no allocation) --------
__device__ float g_Win[Dd*Cc];           // 512 KB
__device__ float g_Wout[Cc*Dd];          // 512 KB
__device__ float g_Wq[(size_t)Kk*Cc];    // 16 MB  (codebook @ W_out^T)
__device__ float g_invn[Kk];             // 1/max(||cb_k||, eps)
__device__ float g_zet[(size_t)Pp*Dd];   // 16 MB  z_e transposed: [pos][d]
__device__ int   g_idx[Pp];
__device__ float g_bestv[2*Pp];          // per-half best value
__device__ int   g_besti[2*Pp];          // per-half best index
__device__ float g_losspart[Pp/64];      // per-64-pos partial loss

// 16 packed FMAs for an 8(pos,paired)x4 microtile step
#define MICRO_FMA2(acc2, aA, aB, b4)                                     \
    do {                                                                 \
        u64 bb0, bb1, bb2, bb3;                                          \
        DUP2(bb0, (b4).x); DUP2(bb1, (b4).y);                            \
        DUP2(bb2, (b4).z); DUP2(bb3, (b4).w);                            \
        FMA2(acc2[0][0], (aA).x, bb0, acc2[0][0]);                       \
        FMA2(acc2[0][1], (aA).x, bb1, acc2[0][1]);                       \
        FMA2(acc2[0][2], (aA).x, bb2, acc2[0][2]);                       \
        FMA2(acc2[0][3], (aA).x, bb3, acc2[0][3]);                       \
        FMA2(acc2[1][0], (aA).y, bb0, acc2[1][0]);                       \
        FMA2(acc2[1][1], (aA).y, bb1, acc2[1][1]);                       \
        FMA2(acc2[1][2], (aA).y, bb2, acc2[1][2]);                       \
        FMA2(acc2[1][3], (aA).y, bb3, acc2[1][3]);                       \
        FMA2(acc2[2][0], (aB).x, bb0, acc2[2][0]);                       \
        FMA2(acc2[2][1], (aB).x, bb1, acc2[2][1]);                       \
        FMA2(acc2[2][2], (aB).x, bb2, acc2[2][2]);                       \
        FMA2(acc2[2][3], (aB).x, bb3, acc2[2][3]);                       \
        FMA2(acc2[3][0], (aB).y, bb0, acc2[3][0]);                       \
        FMA2(acc2[3][1], (aB).y, bb1, acc2[3][1]);                       \
        FMA2(acc2[3][2], (aB).y, bb2, acc2[3][2]);                       \
        FMA2(acc2[3][3], (aB).y, bb3, acc2[3][3]);                       \
    } while (0)

// ================= prep: weight_norm rows =================
__global__ void __launch_bounds__(128) prep_wn_kernel(
    const float* __restrict__ v, const float* __restrict__ g, int cols, int sel)
{
    float* W = sel ? g_Wout : g_Win;
    const int r = blockIdx.x, tid = threadIdx.x;
    float s = 0.f;
    for (int c = tid; c < cols; c += 128) { float t = v[(size_t)r*cols + c]; s = fmaf(t, t, s); }
    #pragma unroll
    for (int m = 16; m; m >>= 1) s += __shfl_xor_sync(0xffffffffu, s, m);
    __shared__ float red[4];
    if ((tid & 31) == 0) red[tid >> 5] = s;
    __syncthreads();
    s = red[0] + red[1] + red[2] + red[3];
    const float scale = g[r] / sqrtf(s);
    for (int c = tid; c < cols; c += 128)
        W[(size_t)r*cols + c] = v[(size_t)r*cols + c] * scale;
}

// ================= prep: codebook inverse norms =================
__global__ void __launch_bounds__(128) prep_cbinv_kernel(const float* __restrict__ cb)
{
    const int r = blockIdx.x, tid = threadIdx.x;
    float s = 0.f;
    for (int c = tid; c < Dd; c += 128) { float t = cb[(size_t)r*Dd + c]; s = fmaf(t, t, s); }
    #pragma unroll
    for (int m = 16; m; m >>= 1) s += __shfl_xor_sync(0xffffffffu, s, m);
    __shared__ float red[4];
    if ((tid & 31) == 0) red[tid >> 5] = s;
    __syncthreads();
    if (tid == 0) {
        s = red[0] + red[1] + red[2] + red[3];
        g_invn[r] = 1.f / fmaxf(sqrtf(s), 1e-8f);
    }
}

// ================= z_e GEMM (R4 version): 64l x 64d tiles =================
__global__ void __launch_bounds__(128) ze_gemm_kernel(
    const float* __restrict__ x, const float* __restrict__ inb)
{
    __shared__ float xs[32][64];    // [c'][l']
    __shared__ float ws[32][68];    // [c'][d'] padded
    const int tid = threadIdx.x, ty = tid >> 4, tx = tid & 15;
    const int l0 = blockIdx.x * 64, d0 = blockIdx.y * 64, n = blockIdx.z;
    const float* xn = x + (size_t)n * Cc * Ll;
    u64 acc2[4][4];
    #pragma unroll
    for (int i = 0; i < 4; i++)
        #pragma unroll
        for (int j = 0; j < 4; j++) acc2[i][j] = 0ull;

    for (int c0 = 0; c0 < Cc; c0 += 32) {
        #pragma unroll
        for (int i = tid; i < 32*64; i += 128) { int c = i >> 6, l = i & 63; xs[c][l] = xn[(size_t)(c0 + c)*Ll + l0 + l]; }
        #pragma unroll
        for (int i = tid; i < 64*32; i += 128) { int d = i >> 5, c = i & 31; ws[c][d] = g_Win[(d0 + d)*Cc + c0 + c]; }
        __syncthreads();
        #pragma unroll 8
        for (int c = 0; c < 32; c++) {
            ulonglong2 aA = *(const ulonglong2*)&xs[c][ty*8];
            ulonglong2 aB = *(const ulonglong2*)&xs[c][ty*8 + 4];
            float4 b = *(const float4*)&ws[c][tx*4];
            MICRO_FMA2(acc2, aA, aB, b);
        }
        __syncthreads();
    }
    const float b0 = inb[d0 + tx*4 + 0], b1 = inb[d0 + tx*4 + 1];
    const float b2 = inb[d0 + tx*4 + 2], b3 = inb[d0 + tx*4 + 3];
    #pragma unroll
    for (int i2 = 0; i2 < 4; i2++) {
        #pragma unroll
        for (int h = 0; h < 2; h++) {
            int l = l0 + ty*8 + i2*2 + h;
            float4 o;
            o.x = (h ? hi32f(acc2[i2][0]) : lo32f(acc2[i2][0])) + b0;
            o.y = (h ? hi32f(acc2[i2][1]) : lo32f(acc2[i2][1])) + b1;
            o.z = (h ? hi32f(acc2[i2][2]) : lo32f(acc2[i2][2])) + b2;
            o.w = (h ? hi32f(acc2[i2][3]) : lo32f(acc2[i2][3])) + b3;
            *(float4*)&g_zet[((size_t)(n*Ll + l))*Dd + d0 + tx*4] = o;
        }
    }
}

// ================= Wq GEMM (R4 version) =================
__global__ void __launch_bounds__(128) wq_gemm_kernel(const float* __restrict__ cb)
{
    __shared__ float as_[32][68];   // [d'][k']
    __shared__ float bs_[32][68];   // [d'][c']
    const int tid = threadIdx.x, ty = tid >> 4, tx = tid & 15;
    const int k0 = blockIdx.x * 64, c0 = blockIdx.y * 64;
    u64 acc2[4][4];
    #pragma unroll
    for (int i = 0; i < 4; i++)
        #pragma unroll
        for (int j = 0; j < 4; j++) acc2[i][j] = 0ull;

    for (int d0 = 0; d0 < Dd; d0 += 32) {
        #pragma unroll
        for (int i = tid; i < 64*32; i += 128) { int k = i >> 5, d = i & 31; as_[d][k] = cb[(size_t)(k0 + k)*Dd + d0 + d]; }
        #pragma unroll
        for (int i = tid; i < 64*32; i += 128) { int c = i >> 5, d = i & 31; bs_[d][c] = g_Wout[(c0 + c)*Dd + d0 + d]; }
        __syncthreads();
        #pragma unroll 8
        for (int d = 0; d < 32; d++) {
            ulonglong2 aA = *(const ulonglong2*)&as_[d][ty*8];
            ulonglong2 aB = *(const ulonglong2*)&as_[d][ty*8 + 4];
            float4 b = *(const float4*)&bs_[d][tx*4];
            MICRO_FMA2(acc2, aA, aB, b);
        }
        __syncthreads();
    }
    #pragma unroll
    for (int i2 = 0; i2 < 4; i2++) {
        #pragma unroll
        for (int h = 0; h < 2; h++) {
            int k = k0 + ty*8 + i2*2 + h;
            float4 o;
            o.x = h ? hi32f(acc2[i2][0]) : lo32f(acc2[i2][0]);
            o.y = h ? hi32f(acc2[i2][1]) : lo32f(acc2[i2][1]);
            o.z = h ? hi32f(acc2[i2][2]) : lo32f(acc2[i2][2]);
            o.w = h ? hi32f(acc2[i2][3]) : lo32f(acc2[i2][3]);
            *(float4*)&g_Wq[(size_t)k*Cc + c0 + tx*4] = o;
        }
    }
}

// ================= split-K search: 64 pos x 4096 codes per block =================
// grid (256, 2): blockIdx.x -> position tile, blockIdx.y -> codebook half.
// 3 blocks/SM (74.2 KB smem each) -> 12 warps/SM residency.
__global__ void __launch_bounds__(128, 3) search_kernel(const float* __restrict__ cb)
{
    extern __shared__ float dynsm[];
    float (*ze)[64]  = (float(*)[64])dynsm;              // [256 d][64 pos]
    float (*cbs)[68] = (float(*)[68])(dynsm + 256*64);   // [32 d][64 code] padded

    const int tid = threadIdx.x, ty = tid >> 4, tx = tid & 15;
    const int p0 = blockIdx.x * 64;
    const int kh = blockIdx.y * (Kk/2);
    const int half = blockIdx.y;

    for (int i = tid; i < 64*256; i += 128) {
        int pos = i >> 8, d = i & 255;
        ze[d][pos] = g_zet[(size_t)(p0 + pos)*Dd + d];
    }
    __syncthreads();

    float best[8]; int bidx[8];
    #pragma unroll
    for (int i = 0; i < 8; i++) { best[i] = -3.4e38f; bidx[i] = 0; }

    // prefetch first chunk (k0=kh, dt=0)
    float4 pre[4];
    #pragma unroll
    for (int j = 0; j < 4; j++) {
        int f = tid + 128*j; int kk = f >> 3, d4 = f & 7;
        pre[j] = *(const float4*)&cb[(size_t)(kh + kk)*Dd + d4*4];
    }

    for (int k0 = kh; k0 < kh + Kk/2; k0 += 64) {
        u64 acc2[4][4];
        #pragma unroll
        for (int i = 0; i < 4; i++)
            #pragma unroll
            for (int j = 0; j < 4; j++) acc2[i][j] = 0ull;

        for (int dt = 0; dt < Dd; dt += 32) {
            #pragma unroll
            for (int j = 0; j < 4; j++) {
                int f = tid + 128*j; int kk = f >> 3, d4 = f & 7;
                cbs[d4*4 + 0][kk] = pre[j].x;
                cbs[d4*4 + 1][kk] = pre[j].y;
                cbs[d4*4 + 2][kk] = pre[j].z;
                cbs[d4*4 + 3][kk] = pre[j].w;
            }
            __syncthreads();
            int ndt = dt + 32, nk0 = k0;
            if (ndt == Dd) { ndt = 0; nk0 = k0 + 64; }
            if (nk0 < kh + Kk/2) {
                #pragma unroll
                for (int j = 0; j < 4; j++) {
                    int f = tid + 128*j; int kk = f >> 3, d4 = f & 7;
                    pre[j] = *(const float4*)&cb[(size_t)(nk0 + kk)*Dd + ndt + d4*4];
                }
            }
            #pragma unroll 8
            for (int d = 0; d < 32; ++d) {
                ulonglong2 aA = *(const ulonglong2*)&ze[dt + d][ty*8];
                ulonglong2 aB = *(const ulonglong2*)&ze[dt + d][ty*8 + 4];
                float4 b = *(const float4*)&cbs[d][tx*4];
                MICRO_FMA2(acc2, aA, aB, b);
            }
            __syncthreads();
        }
        // scale + running argmax (ties -> lowest k via strict >)
        #pragma unroll
        for (int j = 0; j < 4; j++) {
            int k = k0 + tx*4 + j;
            float s = g_invn[k];
            #pragma unroll
            for (int i2 = 0; i2 < 4; i2++) {
                float vlo = lo32f(acc2[i2][j]) * s;
                float vhi = hi32f(acc2[i2][j]) * s;
                if (vlo > best[i2*2])     { best[i2*2]     = vlo; bidx[i2*2]     = k; }
                if (vhi > best[i2*2 + 1]) { best[i2*2 + 1] = vhi; bidx[i2*2 + 1] = k; }
            }
        }
    }

    // reduce over the 16 code-lanes sharing each position group (ties -> lowest k)
    #pragma unroll
    for (int i = 0; i < 8; i++) {
        float b = best[i]; int ix = bidx[i];
        #pragma unroll
        for (int m = 1; m < 16; m <<= 1) {
            float ob = __shfl_xor_sync(0xffffffffu, b, m);
            int   oi = __shfl_xor_sync(0xffffffffu, ix, m);
            if (ob > b || (ob == b && oi < ix)) { b = ob; ix = oi; }
        }
        if (tx == 0) {
            int pos = p0 + ty*8 + i;
            g_bestv[half*Pp + pos] = b;
            g_besti[half*Pp + pos] = ix;
        }
    }
}

// ================= combine halves -> final index =================
__global__ void __launch_bounds__(256) combine_kernel(float* __restrict__ out)
{
    const int p = blockIdx.x * 256 + threadIdx.x;
    float v0 = g_bestv[p],      v1 = g_bestv[Pp + p];
    int   i0 = g_besti[p],      i1 = g_besti[Pp + p];
    int ix = (v1 > v0) ? i1 : i0;   // tie -> lower half -> lower k
    g_idx[p] = ix;
    out[OUT_Y + p] = (float)ix;
}

// ================= VQ loss: sum over d of (cb[idx]-z_e)^2, 64 pos per block =================
__global__ void __launch_bounds__(128) loss_kernel(const float* __restrict__ cb)
{
    __shared__ float lred[4];
    const int tid = threadIdx.x;
    const int p0 = blockIdx.x * 64;
    float ls = 0.f;
    for (int i = tid; i < 64*256; i += 128) {
        int pos = i >> 8, d = i & 255;
        int ix = g_idx[p0 + pos];
        float diff = cb[(size_t)ix*Dd + d] - g_zet[(size_t)(p0 + pos)*Dd + d];
        ls = fmaf(diff, diff, ls);
    }
    #pragma unroll
    for (int m = 16; m; m >>= 1) ls += __shfl_xor_sync(0xffffffffu, ls, m);
    if ((tid & 31) == 0) lred[tid >> 5] = ls;
    __syncthreads();
    if (tid == 0) g_losspart[blockIdx.x] = lred[0] + lred[1] + lred[2] + lred[3];
}

// ================= y gather: y[n][c][l] = Wq[idx[n,l]][c] + out_b[c] =================
__global__ void __launch_bounds__(256) gather_kernel(
    const float* __restrict__ outb, float* __restrict__ out)
{
    extern __shared__ float sm[];   // [32][513]
    __shared__ int sidx[32];
    const int tid = threadIdx.x;
    const int l0 = blockIdx.x * 32, n = blockIdx.y;
    if (tid < 32) sidx[tid] = g_idx[n*Ll + l0 + tid];
    __syncthreads();
    for (int i = tid; i < 32*512; i += 256) {
        int l = i >> 9, c = i & 511;
        sm[l*513 + c] = g_Wq[(size_t)sidx[l]*Cc + c];
    }
    __syncthreads();
    for (int i = tid; i < 512*32; i += 256) {
        int c = i >> 5, l = i & 31;
        out[((size_t)n*Cc + c)*Ll + l0 + l] = sm[l*513 + c] + __ldg(&outb[c]);
    }
}

// ================= finalize losses =================
__global__ void finalize_kernel(float* __restrict__ out)
{
    const int tid = threadIdx.x;            // 128 threads: 4 warps, one per n
    const int n = tid >> 5, lane = tid & 31;
    float s = g_losspart[n*64 + lane] + g_losspart[n*64 + 32 + lane];
    #pragma unroll
    for (int m = 16; m; m >>= 1) s += __shfl_xor_sync(0xffffffffu, s, m);
    if (lane == 0) {
        float v = s * (1.0f / (float)(Dd * Ll));
        out[OUT_LOSS + n]     = v;   // cb_loss
        out[OUT_LOSS + 4 + n] = v;   // cm_loss (numerically identical)
    }
}

// ================= launch =================
extern "C" void kernel_launch(void* const* d_in, const int* in_sizes, int n_in,
                              void* d_out, int out_size)
{
    (void)in_sizes; (void)n_in; (void)out_size;
    const float* x    = (const float*)d_in[0];
    const float* vin  = (const float*)d_in[1];
    const float* gin  = (const float*)d_in[2];
    const float* bin  = (const float*)d_in[3];
    const float* vout = (const float*)d_in[4];
    const float* gout = (const float*)d_in[5];
    const float* bout = (const float*)d_in[6];
    const float* cb   = (const float*)d_in[7];
    float* out = (float*)d_out;

    const int SEARCH_SMEM = (256*64 + 32*68) * 4;   // 74240 B -> 3 blocks/SM
    const int GATHER_SMEM = 32*513*4;               // 65664 B
    cudaFuncSetAttribute(search_kernel, cudaFuncAttributeMaxDynamicSharedMemorySize, SEARCH_SMEM);
    cudaFuncSetAttribute(search_kernel, cudaFuncAttributePreferredSharedMemoryCarveout, 100);
    cudaFuncSetAttribute(gather_kernel, cudaFuncAttributeMaxDynamicSharedMemorySize, GATHER_SMEM);

    prep_wn_kernel<<<Dd, 128>>>(vin, gin, Cc, 0);
    prep_wn_kernel<<<Cc, 128>>>(vout, gout, Dd, 1);
    prep_cbinv_kernel<<<Kk, 128>>>(cb);
    ze_gemm_kernel<<<dim3(Ll/64, Dd/64, Nn), 128>>>(x, bin);
    wq_gemm_kernel<<<dim3(Kk/64, Cc/64), 128>>>(cb);
    search_kernel<<<dim3(Pp/64, 2), 128, SEARCH_SMEM>>>(cb);
    combine_kernel<<<Pp/256, 256>>>(out);
    loss_kernel<<<Pp/64, 128>>>(cb);
    gather_kernel<<<dim3(Ll/32, Nn), 256, GATHER_SMEM>>>(bout, out);
    finalize_kernel<<<1, 128>>>(out);
}

// round 9
// speedup vs baseline: 1.3096x; 1.1199x over previous
#include <cuda_runtime.h>
#include <math.h>

#define Nn 4
#define Cc 512
#define Ll 4096
#define Dd 256
#define Kk 8192
#define Pp (Nn*Ll)               // 16384 positions
#define OUT_Y ((size_t)Nn*Cc*Ll) // 8388608
#define OUT_LOSS (OUT_Y + Pp)    // 8404992

#define NSLICE 8                 // k-slices per position tile (1024 codes each)
#define NPT    (Pp/64)           // 256 position tiles
#define NITEMS (NPT*NSLICE)      // 2048 work items
#define SLICEK (Kk/NSLICE)       // 1024 codes
#define GRID_PERSIST (152*3)     // 3 blocks/SM on GB300 (152 SMs)

typedef unsigned long long u64;

// packed fp32x2 FMA (sm_103a): 2 IEEE fp32 FMAs per instruction, bit-exact
#define FMA2(d, a, b, c) \
    asm("fma.rn.f32x2 %0, %1, %2, %3;" : "=l"(d) : "l"(a), "l"(b), "l"(c))
#define DUP2(d, s) \
    asm("mov.b64 %0, {%1, %1};" : "=l"(d) : "f"(s))

__device__ __forceinline__ float lo32f(u64 v) { return __uint_as_float((unsigned)(v & 0xffffffffu)); }
__device__ __forceinline__ float hi32f(u64 v) { return __uint_as_float((unsigned)(v >> 32)); }

// -------- device scratch (static, no allocation) --------
__device__ float g_Win[Dd*Cc];           // 512 KB
__device__ float g_Wout[Cc*Dd];          // 512 KB
__device__ float g_Wq[(size_t)Kk*Cc];    // 16 MB  (codebook @ W_out^T)
__device__ float g_invn[Kk];             // 1/max(||cb_k||, eps)
__device__ float g_zet[(size_t)Pp*Dd];   // 16 MB  z_e transposed: [pos][d]
__device__ int   g_idx[Pp];
__device__ float g_bestv[NSLICE*Pp];     // per-slice best value
__device__ int   g_besti[NSLICE*Pp];     // per-slice best index
__device__ float g_losspart[Pp/64];      // per-64-pos partial loss
__device__ int   g_work;                 // persistent work counter

// 16 packed FMAs for an 8(pos,paired)x4 microtile step
// NOTE: lo/hi lanes of each accumulator are two adjacent POSITIONS
// sharing the same code k (code operand is duplicated into both lanes).
#define MICRO_FMA2(acc2, aA, aB, b4)                                     \
    do {                                                                 \
        u64 bb0, bb1, bb2, bb3;                                          \
        DUP2(bb0, (b4).x); DUP2(bb1, (b4).y);                            \
        DUP2(bb2, (b4).z); DUP2(bb3, (b4).w);                            \
        FMA2(acc2[0][0], (aA).x, bb0, acc2[0][0]);                       \
        FMA2(acc2[0][1], (aA).x, bb1, acc2[0][1]);                       \
        FMA2(acc2[0][2], (aA).x, bb2, acc2[0][2]);                       \
        FMA2(acc2[0][3], (aA).x, bb3, acc2[0][3]);                       \
        FMA2(acc2[1][0], (aA).y, bb0, acc2[1][0]);                       \
        FMA2(acc2[1][1], (aA).y, bb1, acc2[1][1]);                       \
        FMA2(acc2[1][2], (aA).y, bb2, acc2[1][2]);                       \
        FMA2(acc2[1][3], (aA).y, bb3, acc2[1][3]);                       \
        FMA2(acc2[2][0], (aB).x, bb0, acc2[2][0]);                       \
        FMA2(acc2[2][1], (aB).x, bb1, acc2[2][1]);                       \
        FMA2(acc2[2][2], (aB).x, bb2, acc2[2][2]);                       \
        FMA2(acc2[2][3], (aB).x, bb3, acc2[2][3]);                       \
        FMA2(acc2[3][0], (aB).y, bb0, acc2[3][0]);                       \
        FMA2(acc2[3][1], (aB).y, bb1, acc2[3][1]);                       \
        FMA2(acc2[3][2], (aB).y, bb2, acc2[3][2]);                       \
        FMA2(acc2[3][3], (aB).y, bb3, acc2[3][3]);                       \
    } while (0)

// ================= prep: weight_norm rows =================
__global__ void __launch_bounds__(128) prep_wn_kernel(
    const float* __restrict__ v, const float* __restrict__ g, int cols, int sel)
{
    float* W = sel ? g_Wout : g_Win;
    const int r = blockIdx.x, tid = threadIdx.x;
    float s = 0.f;
    for (int c = tid; c < cols; c += 128) { float t = v[(size_t)r*cols + c]; s = fmaf(t, t, s); }
    #pragma unroll
    for (int m = 16; m; m >>= 1) s += __shfl_xor_sync(0xffffffffu, s, m);
    __shared__ float red[4];
    if ((tid & 31) == 0) red[tid >> 5] = s;
    __syncthreads();
    s = red[0] + red[1] + red[2] + red[3];
    const float scale = g[r] / sqrtf(s);
    for (int c = tid; c < cols; c += 128)
        W[(size_t)r*cols + c] = v[(size_t)r*cols + c] * scale;
}

// ================= prep: codebook inverse norms (+work counter reset) =================
__global__ void __launch_bounds__(128) prep_cbinv_kernel(const float* __restrict__ cb)
{
    const int r = blockIdx.x, tid = threadIdx.x;
    if (r == 0 && tid == 0) g_work = 0;
    float s = 0.f;
    for (int c = tid; c < Dd; c += 128) { float t = cb[(size_t)r*Dd + c]; s = fmaf(t, t, s); }
    #pragma unroll
    for (int m = 16; m; m >>= 1) s += __shfl_xor_sync(0xffffffffu, s, m);
    __shared__ float red[4];
    if ((tid & 31) == 0) red[tid >> 5] = s;
    __syncthreads();
    if (tid == 0) {
        s = red[0] + red[1] + red[2] + red[3];
        g_invn[r] = 1.f / fmaxf(sqrtf(s), 1e-8f);
    }
}

// ================= z_e GEMM: 64l x 64d tiles =================
__global__ void __launch_bounds__(128) ze_gemm_kernel(
    const float* __restrict__ x, const float* __restrict__ inb)
{
    __shared__ float xs[32][64];    // [c'][l']
    __shared__ float ws[32][68];    // [c'][d'] padded
    const int tid = threadIdx.x, ty = tid >> 4, tx = tid & 15;
    const int l0 = blockIdx.x * 64, d0 = blockIdx.y * 64, n = blockIdx.z;
    const float* xn = x + (size_t)n * Cc * Ll;
    u64 acc2[4][4];
    #pragma unroll
    for (int i = 0; i < 4; i++)
        #pragma unroll
        for (int j = 0; j < 4; j++) acc2[i][j] = 0ull;

    for (int c0 = 0; c0 < Cc; c0 += 32) {
        #pragma unroll
        for (int i = tid; i < 32*64; i += 128) { int c = i >> 6, l = i & 63; xs[c][l] = xn[(size_t)(c0 + c)*Ll + l0 + l]; }
        #pragma unroll
        for (int i = tid; i < 64*32; i += 128) { int d = i >> 5, c = i & 31; ws[c][d] = g_Win[(d0 + d)*Cc + c0 + c]; }
        __syncthreads();
        #pragma unroll 8
        for (int c = 0; c < 32; c++) {
            ulonglong2 aA = *(const ulonglong2*)&xs[c][ty*8];
            ulonglong2 aB = *(const ulonglong2*)&xs[c][ty*8 + 4];
            float4 b = *(const float4*)&ws[c][tx*4];
            MICRO_FMA2(acc2, aA, aB, b);
        }
        __syncthreads();
    }
    const float b0 = inb[d0 + tx*4 + 0], b1 = inb[d0 + tx*4 + 1];
    const float b2 = inb[d0 + tx*4 + 2], b3 = inb[d0 + tx*4 + 3];
    #pragma unroll
    for (int i2 = 0; i2 < 4; i2++) {
        #pragma unroll
        for (int h = 0; h < 2; h++) {
            int l = l0 + ty*8 + i2*2 + h;
            float4 o;
            o.x = (h ? hi32f(acc2[i2][0]) : lo32f(acc2[i2][0])) + b0;
            o.y = (h ? hi32f(acc2[i2][1]) : lo32f(acc2[i2][1])) + b1;
            o.z = (h ? hi32f(acc2[i2][2]) : lo32f(acc2[i2][2])) + b2;
            o.w = (h ? hi32f(acc2[i2][3]) : lo32f(acc2[i2][3])) + b3;
            *(float4*)&g_zet[((size_t)(n*Ll + l))*Dd + d0 + tx*4] = o;
        }
    }
}

// ================= Wq GEMM =================
__global__ void __launch_bounds__(128) wq_gemm_kernel(const float* __restrict__ cb)
{
    __shared__ float as_[32][68];   // [d'][k']
    __shared__ float bs_[32][68];   // [d'][c']
    const int tid = threadIdx.x, ty = tid >> 4, tx = tid & 15;
    const int k0 = blockIdx.x * 64, c0 = blockIdx.y * 64;
    u64 acc2[4][4];
    #pragma unroll
    for (int i = 0; i < 4; i++)
        #pragma unroll
        for (int j = 0; j < 4; j++) acc2[i][j] = 0ull;

    for (int d0 = 0; d0 < Dd; d0 += 32) {
        #pragma unroll
        for (int i = tid; i < 64*32; i += 128) { int k = i >> 5, d = i & 31; as_[d][k] = cb[(size_t)(k0 + k)*Dd + d0 + d]; }
        #pragma unroll
        for (int i = tid; i < 64*32; i += 128) { int c = i >> 5, d = i & 31; bs_[d][c] = g_Wout[(c0 + c)*Dd + d0 + d]; }
        __syncthreads();
        #pragma unroll 8
        for (int d = 0; d < 32; d++) {
            ulonglong2 aA = *(const ulonglong2*)&as_[d][ty*8];
            ulonglong2 aB = *(const ulonglong2*)&as_[d][ty*8 + 4];
            float4 b = *(const float4*)&bs_[d][tx*4];
            MICRO_FMA2(acc2, aA, aB, b);
        }
        __syncthreads();
    }
    #pragma unroll
    for (int i2 = 0; i2 < 4; i2++) {
        #pragma unroll
        for (int h = 0; h < 2; h++) {
            int k = k0 + ty*8 + i2*2 + h;
            float4 o;
            o.x = h ? hi32f(acc2[i2][0]) : lo32f(acc2[i2][0]);
            o.y = h ? hi32f(acc2[i2][1]) : lo32f(acc2[i2][1]);
            o.z = h ? hi32f(acc2[i2][2]) : lo32f(acc2[i2][2]);
            o.w = h ? hi32f(acc2[i2][3]) : lo32f(acc2[i2][3]);
            *(float4*)&g_Wq[(size_t)k*Cc + c0 + tx*4] = o;
        }
    }
}

// ================= persistent split-K search =================
// Work item = (pos-tile of 64, k-slice of 1024 codes). 2048 items pulled
// from a global counter by 456 persistent blocks (3/SM). Output per
// (pos, slice): best value + index; combined exactly afterwards.
__global__ void __launch_bounds__(128, 3) search_kernel(const float* __restrict__ cb)
{
    extern __shared__ float dynsm[];
    float (*ze)[64]  = (float(*)[64])dynsm;              // [256 d][64 pos]
    float (*cbs)[68] = (float(*)[68])(dynsm + 256*64);   // [32 d][64 code] padded
    __shared__ int s_item;

    const int tid = threadIdx.x, ty = tid >> 4, tx = tid & 15;
    int last_pt = -1;

    for (;;) {
        __syncthreads();   // previous item fully done before s_item/ze overwrite
        if (tid == 0) s_item = atomicAdd(&g_work, 1);
        __syncthreads();
        const int item = s_item;
        if (item >= NITEMS) break;
        const int pt = item >> 3;            // position tile
        const int slice = item & (NSLICE-1); // k-slice
        const int p0 = pt * 64;
        const int kh = slice * SLICEK;

        if (pt != last_pt) {
            for (int i = tid; i < 64*256; i += 128) {
                int pos = i >> 8, d = i & 255;
                ze[d][pos] = g_zet[(size_t)(p0 + pos)*Dd + d];
            }
            last_pt = pt;
        }
        __syncthreads();

        float best[8]; int bidx[8];
        #pragma unroll
        for (int i = 0; i < 8; i++) { best[i] = -3.4e38f; bidx[i] = 0; }

        // prefetch first chunk (k0=kh, dt=0)
        float4 pre[4];
        #pragma unroll
        for (int j = 0; j < 4; j++) {
            int f = tid + 128*j; int kk = f >> 3, d4 = f & 7;
            pre[j] = *(const float4*)&cb[(size_t)(kh + kk)*Dd + d4*4];
        }

        for (int k0 = kh; k0 < kh + SLICEK; k0 += 64) {
            u64 acc2[4][4];
            #pragma unroll
            for (int i = 0; i < 4; i++)
                #pragma unroll
                for (int j = 0; j < 4; j++) acc2[i][j] = 0ull;

            for (int dt = 0; dt < Dd; dt += 32) {
                #pragma unroll
                for (int j = 0; j < 4; j++) {
                    int f = tid + 128*j; int kk = f >> 3, d4 = f & 7;
                    cbs[d4*4 + 0][kk] = pre[j].x;
                    cbs[d4*4 + 1][kk] = pre[j].y;
                    cbs[d4*4 + 2][kk] = pre[j].z;
                    cbs[d4*4 + 3][kk] = pre[j].w;
                }
                __syncthreads();
                int ndt = dt + 32, nk0 = k0;
                if (ndt == Dd) { ndt = 0; nk0 = k0 + 64; }
                if (nk0 < kh + SLICEK) {
                    #pragma unroll
                    for (int j = 0; j < 4; j++) {
                        int f = tid + 128*j; int kk = f >> 3, d4 = f & 7;
                        pre[j] = *(const float4*)&cb[(size_t)(nk0 + kk)*Dd + ndt + d4*4];
                    }
                }
                #pragma unroll 8
                for (int d = 0; d < 32; ++d) {
                    ulonglong2 aA = *(const ulonglong2*)&ze[dt + d][ty*8];
                    ulonglong2 aB = *(const ulonglong2*)&ze[dt + d][ty*8 + 4];
                    float4 b = *(const float4*)&cbs[d][tx*4];
                    MICRO_FMA2(acc2, aA, aB, b);
                }
                __syncthreads();
            }
            // scale + running argmax (ties -> lowest k via strict >)
            // lo/hi lanes are two adjacent positions for the SAME code k.
            #pragma unroll
            for (int j = 0; j < 4; j++) {
                int k = k0 + tx*4 + j;
                float s = g_invn[k];
                #pragma unroll
                for (int i2 = 0; i2 < 4; i2++) {
                    float vlo = lo32f(acc2[i2][j]) * s;
                    float vhi = hi32f(acc2[i2][j]) * s;
                    if (vlo > best[i2*2])     { best[i2*2]     = vlo; bidx[i2*2]     = k; }
                    if (vhi > best[i2*2 + 1]) { best[i2*2 + 1] = vhi; bidx[i2*2 + 1] = k; }
                }
            }
        }

        // reduce over the 16 code-lanes per position group (ties -> lowest k)
        #pragma unroll
        for (int i = 0; i < 8; i++) {
            float b = best[i]; int ix = bidx[i];
            #pragma unroll
            for (int m = 1; m < 16; m <<= 1) {
                float ob = __shfl_xor_sync(0xffffffffu, b, m);
                int   oi = __shfl_xor_sync(0xffffffffu, ix, m);
                if (ob > b || (ob == b && oi < ix)) { b = ob; ix = oi; }
            }
            if (tx == 0) {
                int pos = p0 + ty*8 + i;
                g_bestv[(size_t)slice*Pp + pos] = b;
                g_besti[(size_t)slice*Pp + pos] = ix;
            }
        }
    }
}

// ================= combine slices -> final index =================
__global__ void __launch_bounds__(256) combine_kernel(float* __restrict__ out)
{
    const int p = blockIdx.x * 256 + threadIdx.x;
    float bv = g_bestv[p];
    int   bi = g_besti[p];
    #pragma unroll
    for (int s = 1; s < NSLICE; s++) {
        float v = g_bestv[(size_t)s*Pp + p];
        int   i = g_besti[(size_t)s*Pp + p];
        if (v > bv) { bv = v; bi = i; }   // slices k-ordered: strict > keeps lowest k
    }
    g_idx[p] = bi;
    out[OUT_Y + p] = (float)bi;
}

// ================= VQ loss =================
__global__ void __launch_bounds__(128) loss_kernel(const float* __restrict__ cb)
{
    __shared__ float lred[4];
    const int tid = threadIdx.x;
    const int p0 = blockIdx.x * 64;
    float ls = 0.f;
    for (int i = tid; i < 64*256; i += 128) {
        int pos = i >> 8, d = i & 255;
        int ix = g_idx[p0 + pos];
        float diff = cb[(size_t)ix*Dd + d] - g_zet[(size_t)(p0 + pos)*Dd + d];
        ls = fmaf(diff, diff, ls);
    }
    #pragma unroll
    for (int m = 16; m; m >>= 1) ls += __shfl_xor_sync(0xffffffffu, ls, m);
    if ((tid & 31) == 0) lred[tid >> 5] = ls;
    __syncthreads();
    if (tid == 0) g_losspart[blockIdx.x] = lred[0] + lred[1] + lred[2] + lred[3];
}

// ================= y gather: y[n][c][l] = Wq[idx[n,l]][c] + out_b[c] =================
__global__ void __launch_bounds__(256) gather_kernel(
    const float* __restrict__ outb, float* __restrict__ out)
{
    extern __shared__ float sm[];   // [32][513]
    __shared__ int sidx[32];
    const int tid = threadIdx.x;
    const int l0 = blockIdx.x * 32, n = blockIdx.y;
    if (tid < 32) sidx[tid] = g_idx[n*Ll + l0 + tid];
    __syncthreads();
    for (int i = tid; i < 32*512; i += 256) {
        int l = i >> 9, c = i & 511;
        sm[l*513 + c] = g_Wq[(size_t)sidx[l]*Cc + c];
    }
    __syncthreads();
    for (int i = tid; i < 512*32; i += 256) {
        int c = i >> 5, l = i & 31;
        out[((size_t)n*Cc + c)*Ll + l0 + l] = sm[l*513 + c] + __ldg(&outb[c]);
    }
}

// ================= finalize losses =================
__global__ void finalize_kernel(float* __restrict__ out)
{
    const int tid = threadIdx.x;            // 128 threads: 4 warps, one per n
    const int n = tid >> 5, lane = tid & 31;
    float s = g_losspart[n*64 + lane] + g_losspart[n*64 + 32 + lane];
    #pragma unroll
    for (int m = 16; m; m >>= 1) s += __shfl_xor_sync(0xffffffffu, s, m);
    if (lane == 0) {
        float v = s * (1.0f / (float)(Dd * Ll));
        out[OUT_LOSS + n]     = v;   // cb_loss
        out[OUT_LOSS + 4 + n] = v;   // cm_loss (numerically identical)
    }
}

// ================= launch =================
extern "C" void kernel_launch(void* const* d_in, const int* in_sizes, int n_in,
                              void* d_out, int out_size)
{
    (void)in_sizes; (void)n_in; (void)out_size;
    const float* x    = (const float*)d_in[0];
    const float* vin  = (const float*)d_in[1];
    const float* gin  = (const float*)d_in[2];
    const float* bin  = (const float*)d_in[3];
    const float* vout = (const float*)d_in[4];
    const float* gout = (const float*)d_in[5];
    const float* bout = (const float*)d_in[6];
    const float* cb   = (const float*)d_in[7];
    float* out = (float*)d_out;

    const int SEARCH_SMEM = (256*64 + 32*68) * 4;   // 74240 B -> 3 blocks/SM
    const int GATHER_SMEM = 32*513*4;               // 65664 B
    cudaFuncSetAttribute(search_kernel, cudaFuncAttributeMaxDynamicSharedMemorySize, SEARCH_SMEM);
    cudaFuncSetAttribute(search_kernel, cudaFuncAttributePreferredSharedMemoryCarveout, 100);
    cudaFuncSetAttribute(gather_kernel, cudaFuncAttributeMaxDynamicSharedMemorySize, GATHER_SMEM);

    prep_wn_kernel<<<Dd, 128>>>(vin, gin, Cc, 0);
    prep_wn_kernel<<<Cc, 128>>>(vout, gout, Dd, 1);
    prep_cbinv_kernel<<<Kk, 128>>>(cb);   // also resets g_work
    ze_gemm_kernel<<<dim3(Ll/64, Dd/64, Nn), 128>>>(x, bin);
    wq_gemm_kernel<<<dim3(Kk/64, Cc/64), 128>>>(cb);
    search_kernel<<<GRID_PERSIST, 128, SEARCH_SMEM>>>(cb);
    combine_kernel<<<Pp/256, 256>>>(out);
    loss_kernel<<<Pp/64, 128>>>(cb);
    gather_kernel<<<dim3(Ll/32, Nn), 256, GATHER_SMEM>>>(bout, out);
    finalize_kernel<<<1, 128>>>(out);
}

// round 10
// speedup vs baseline: 1.3827x; 1.0558x over previous
#include <cuda_runtime.h>
#include <math.h>

#define Nn 4
#define Cc 512
#define Ll 4096
#define Dd 256
#define Kk 8192
#define Pp (Nn*Ll)               // 16384 positions
#define OUT_Y ((size_t)Nn*Cc*Ll) // 8388608
#define OUT_LOSS (OUT_Y + Pp)    // 8404992

#define NSLICE 16                // k-slices per position tile (512 codes each)
#define NPT    (Pp/64)           // 256 position tiles
#define NITEMS (NPT*NSLICE)      // 4096 work items
#define SLICEK (Kk/NSLICE)       // 512 codes
#define WKCODES (SLICEK/4)       // 128 codes per warp per item
#define NCHUNK (WKCODES/16)      // 8 k-chunks of 16 codes per warp
#define GRID_PERSIST (152*3)     // 3 blocks/SM on GB300 (152 SMs)

typedef unsigned long long u64;

// packed fp32x2 FMA (sm_103a): 2 IEEE fp32 FMAs per instruction, bit-exact
#define FMA2(d, a, b, c) \
    asm("fma.rn.f32x2 %0, %1, %2, %3;" : "=l"(d) : "l"(a), "l"(b), "l"(c))
#define DUP2(d, s) \
    asm("mov.b64 %0, {%1, %1};" : "=l"(d) : "f"(s))

__device__ __forceinline__ float lo32f(u64 v) { return __uint_as_float((unsigned)(v & 0xffffffffu)); }
__device__ __forceinline__ float hi32f(u64 v) { return __uint_as_float((unsigned)(v >> 32)); }

// -------- device scratch (static, no allocation) --------
__device__ float g_Win[Dd*Cc];           // 512 KB
__device__ float g_Wout[Cc*Dd];          // 512 KB
__device__ float g_Wq[(size_t)Kk*Cc];    // 16 MB  (codebook @ W_out^T)
__device__ float g_invn[Kk];             // 1/max(||cb_k||, eps)
__device__ float g_zet[(size_t)Pp*Dd];   // 16 MB  z_e transposed: [pos][d]
__device__ int   g_idx[Pp];
__device__ float g_bestv[(size_t)NSLICE*Pp];  // per-slice best value
__device__ int   g_besti[(size_t)NSLICE*Pp];  // per-slice best index
__device__ float g_losspart[Pp/64];      // per-64-pos partial loss
__device__ int   g_work;                 // persistent work counter

// 16 packed FMAs for an 8(pos,paired)x4 microtile step
// NOTE: lo/hi lanes of each accumulator are two adjacent POSITIONS
// sharing the same code k (code operand is duplicated into both lanes).
#define MICRO_FMA2(acc2, aA, aB, b4)                                     \
    do {                                                                 \
        u64 bb0, bb1, bb2, bb3;                                          \
        DUP2(bb0, (b4).x); DUP2(bb1, (b4).y);                            \
        DUP2(bb2, (b4).z); DUP2(bb3, (b4).w);                            \
        FMA2(acc2[0][0], (aA).x, bb0, acc2[0][0]);                       \
        FMA2(acc2[0][1], (aA).x, bb1, acc2[0][1]);                       \
        FMA2(acc2[0][2], (aA).x, bb2, acc2[0][2]);                       \
        FMA2(acc2[0][3], (aA).x, bb3, acc2[0][3]);                       \
        FMA2(acc2[1][0], (aA).y, bb0, acc2[1][0]);                       \
        FMA2(acc2[1][1], (aA).y, bb1, acc2[1][1]);                       \
        FMA2(acc2[1][2], (aA).y, bb2, acc2[1][2]);                       \
        FMA2(acc2[1][3], (aA).y, bb3, acc2[1][3]);                       \
        FMA2(acc2[2][0], (aB).x, bb0, acc2[2][0]);                       \
        FMA2(acc2[2][1], (aB).x, bb1, acc2[2][1]);                       \
        FMA2(acc2[2][2], (aB).x, bb2, acc2[2][2]);                       \
        FMA2(acc2[2][3], (aB).x, bb3, acc2[2][3]);                       \
        FMA2(acc2[3][0], (aB).y, bb0, acc2[3][0]);                       \
        FMA2(acc2[3][1], (aB).y, bb1, acc2[3][1]);                       \
        FMA2(acc2[3][2], (aB).y, bb2, acc2[3][2]);                       \
        FMA2(acc2[3][3], (aB).y, bb3, acc2[3][3]);                       \
    } while (0)

// ================= prep: weight_norm rows =================
__global__ void __launch_bounds__(128) prep_wn_kernel(
    const float* __restrict__ v, const float* __restrict__ g, int cols, int sel)
{
    float* W = sel ? g_Wout : g_Win;
    const int r = blockIdx.x, tid = threadIdx.x;
    float s = 0.f;
    for (int c = tid; c < cols; c += 128) { float t = v[(size_t)r*cols + c]; s = fmaf(t, t, s); }
    #pragma unroll
    for (int m = 16; m; m >>= 1) s += __shfl_xor_sync(0xffffffffu, s, m);
    __shared__ float red[4];
    if ((tid & 31) == 0) red[tid >> 5] = s;
    __syncthreads();
    s = red[0] + red[1] + red[2] + red[3];
    const float scale = g[r] / sqrtf(s);
    for (int c = tid; c < cols; c += 128)
        W[(size_t)r*cols + c] = v[(size_t)r*cols + c] * scale;
}

// ================= prep: codebook inverse norms (+work counter reset) =================
__global__ void __launch_bounds__(128) prep_cbinv_kernel(const float* __restrict__ cb)
{
    const int r = blockIdx.x, tid = threadIdx.x;
    if (r == 0 && tid == 0) g_work = 0;
    float s = 0.f;
    for (int c = tid; c < Dd; c += 128) { float t = cb[(size_t)r*Dd + c]; s = fmaf(t, t, s); }
    #pragma unroll
    for (int m = 16; m; m >>= 1) s += __shfl_xor_sync(0xffffffffu, s, m);
    __shared__ float red[4];
    if ((tid & 31) == 0) red[tid >> 5] = s;
    __syncthreads();
    if (tid == 0) {
        s = red[0] + red[1] + red[2] + red[3];
        g_invn[r] = 1.f / fmaxf(sqrtf(s), 1e-8f);
    }
}

// ================= z_e GEMM: 64l x 64d tiles =================
__global__ void __launch_bounds__(128) ze_gemm_kernel(
    const float* __restrict__ x, const float* __restrict__ inb)
{
    __shared__ float xs[32][64];    // [c'][l']
    __shared__ float ws[32][68];    // [c'][d'] padded
    const int tid = threadIdx.x, ty = tid >> 4, tx = tid & 15;
    const int l0 = blockIdx.x * 64, d0 = blockIdx.y * 64, n = blockIdx.z;
    const float* xn = x + (size_t)n * Cc * Ll;
    u64 acc2[4][4];
    #pragma unroll
    for (int i = 0; i < 4; i++)
        #pragma unroll
        for (int j = 0; j < 4; j++) acc2[i][j] = 0ull;

    for (int c0 = 0; c0 < Cc; c0 += 32) {
        #pragma unroll
        for (int i = tid; i < 32*64; i += 128) { int c = i >> 6, l = i & 63; xs[c][l] = xn[(size_t)(c0 + c)*Ll + l0 + l]; }
        #pragma unroll
        for (int i = tid; i < 64*32; i += 128) { int d = i >> 5, c = i & 31; ws[c][d] = g_Win[(d0 + d)*Cc + c0 + c]; }
        __syncthreads();
        #pragma unroll 8
        for (int c = 0; c < 32; c++) {
            ulonglong2 aA = *(const ulonglong2*)&xs[c][ty*8];
            ulonglong2 aB = *(const ulonglong2*)&xs[c][ty*8 + 4];
            float4 b = *(const float4*)&ws[c][tx*4];
            MICRO_FMA2(acc2, aA, aB, b);
        }
        __syncthreads();
    }
    const float b0 = inb[d0 + tx*4 + 0], b1 = inb[d0 + tx*4 + 1];
    const float b2 = inb[d0 + tx*4 + 2], b3 = inb[d0 + tx*4 + 3];
    #pragma unroll
    for (int i2 = 0; i2 < 4; i2++) {
        #pragma unroll
        for (int h = 0; h < 2; h++) {
            int l = l0 + ty*8 + i2*2 + h;
            float4 o;
            o.x = (h ? hi32f(acc2[i2][0]) : lo32f(acc2[i2][0])) + b0;
            o.y = (h ? hi32f(acc2[i2][1]) : lo32f(acc2[i2][1])) + b1;
            o.z = (h ? hi32f(acc2[i2][2]) : lo32f(acc2[i2][2])) + b2;
            o.w = (h ? hi32f(acc2[i2][3]) : lo32f(acc2[i2][3])) + b3;
            *(float4*)&g_zet[((size_t)(n*Ll + l))*Dd + d0 + tx*4] = o;
        }
    }
}

// ================= Wq GEMM =================
__global__ void __launch_bounds__(128) wq_gemm_kernel(const float* __restrict__ cb)
{
    __shared__ float as_[32][68];   // [d'][k']
    __shared__ float bs_[32][68];   // [d'][c']
    const int tid = threadIdx.x, ty = tid >> 4, tx = tid & 15;
    const int k0 = blockIdx.x * 64, c0 = blockIdx.y * 64;
    u64 acc2[4][4];
    #pragma unroll
    for (int i = 0; i < 4; i++)
        #pragma unroll
        for (int j = 0; j < 4; j++) acc2[i][j] = 0ull;

    for (int d0 = 0; d0 < Dd; d0 += 32) {
        #pragma unroll
        for (int i = tid; i < 64*32; i += 128) { int k = i >> 5, d = i & 31; as_[d][k] = cb[(size_t)(k0 + k)*Dd + d0 + d]; }
        #pragma unroll
        for (int i = tid; i < 64*32; i += 128) { int c = i >> 5, d = i & 31; bs_[d][c] = g_Wout[(c0 + c)*Dd + d0 + d]; }
        __syncthreads();
        #pragma unroll 8
        for (int d = 0; d < 32; d++) {
            ulonglong2 aA = *(const ulonglong2*)&as_[d][ty*8];
            ulonglong2 aB = *(const ulonglong2*)&as_[d][ty*8 + 4];
            float4 b = *(const float4*)&bs_[d][tx*4];
            MICRO_FMA2(acc2, aA, aB, b);
        }
        __syncthreads();
    }
    #pragma unroll
    for (int i2 = 0; i2 < 4; i2++) {
        #pragma unroll
        for (int h = 0; h < 2; h++) {
            int k = k0 + ty*8 + i2*2 + h;
            float4 o;
            o.x = h ? hi32f(acc2[i2][0]) : lo32f(acc2[i2][0]);
            o.y = h ? hi32f(acc2[i2][1]) : lo32f(acc2[i2][1]);
            o.z = h ? hi32f(acc2[i2][2]) : lo32f(acc2[i2][2]);
            o.w = h ? hi32f(acc2[i2][3]) : lo32f(acc2[i2][3]);
            *(float4*)&g_Wq[(size_t)k*Cc + c0 + tx*4] = o;
        }
    }
}

// ================= persistent warp-autonomous split-K search =================
// Work item = (pos-tile of 64, k-slice of 512 codes). 4096 items pulled from a
// global counter by 456 persistent blocks (3/SM). Within an item each warp
// autonomously scans its own 128-code quarter using a warp-private smem
// staging buffer (no block-wide barriers in the mainloop).
__global__ void __launch_bounds__(128, 3) search_kernel(const float* __restrict__ cb)
{
    extern __shared__ float dynsm[];
    float (*ze)[64] = (float(*)[64])dynsm;   // [256 d][64 pos]  (65536 B)
    float* cbs = dynsm + 256*64;             // [4 warps][32 d][16 codes] (8192 B)
    __shared__ float sbv[4][64];
    __shared__ int   sbi[4][64];
    __shared__ int   s_item;

    const int tid = threadIdx.x;
    const int wid = tid >> 5, lane = tid & 31;
    const int pg = lane >> 2, cg = lane & 3;     // pos-group / code-group
    const int kl = lane >> 1, dh = lane & 1;     // staging load mapping
    float* cbw = cbs + wid * (32*16);            // this warp's private buffer

    int last_pt = -1;

    for (;;) {
        __syncthreads();   // previous item fully consumed before s_item/ze overwrite
        if (tid == 0) s_item = atomicAdd(&g_work, 1);
        __syncthreads();
        const int item = s_item;
        if (item >= NITEMS) break;
        const int pt = item >> 4;                // position tile (slices of a pt are consecutive)
        const int slice = item & (NSLICE-1);
        const int p0 = pt * 64;
        const int kw = slice*SLICEK + wid*WKCODES;   // this warp's code-range base

        if (pt != last_pt) {
            // conflict-free transposed load: warp covers 32 positions per d-quad
            #pragma unroll 4
            for (int it = 0; it < 32; it++) {
                int flat = it*128 + tid;
                int pos = flat & 63, d4 = flat >> 6;
                float4 v = *(const float4*)&g_zet[(size_t)(p0 + pos)*Dd + d4*4];
                ze[d4*4 + 0][pos] = v.x; ze[d4*4 + 1][pos] = v.y;
                ze[d4*4 + 2][pos] = v.z; ze[d4*4 + 3][pos] = v.w;
            }
            last_pt = pt;
            __syncthreads();   // publish ze to all warps
        }

        float best[8]; int bidx[8];
        #pragma unroll
        for (int i = 0; i < 8; i++) { best[i] = -3.4e38f; bidx[i] = 0; }

        // prefetch segment 0 (chunk 0, d-chunk 0): 16 codes x 32 d per warp
        float4 pre[4];
        {
            const float* src = &cb[(size_t)(kw + kl)*Dd + dh*16];
            #pragma unroll
            for (int i = 0; i < 4; i++) pre[i] = *(const float4*)&src[i*4];
        }

        for (int c = 0; c < NCHUNK; c++) {
            const int kc = kw + c*16;
            float4 iv = *(const float4*)&g_invn[kc + cg*4];
            u64 acc2[4][4];
            #pragma unroll
            for (int i = 0; i < 4; i++)
                #pragma unroll
                for (int j = 0; j < 4; j++) acc2[i][j] = 0ull;

            for (int dc = 0; dc < 8; dc++) {
                __syncwarp();   // prior segment's LDS of cbw done before overwrite
                // commit: cbw[d_local][k_local], d_local = dh*16 + i*4 + j
                #pragma unroll
                for (int i = 0; i < 4; i++) {
                    float* dst = &cbw[(dh*16 + i*4)*16 + kl];
                    dst[0]  = pre[i].x;
                    dst[16] = pre[i].y;
                    dst[32] = pre[i].z;
                    dst[48] = pre[i].w;
                }
                __syncwarp();
                // prefetch next segment (warp-local pipelining)
                int nc = c, ndc = dc + 1;
                if (ndc == 8) { ndc = 0; nc = c + 1; }
                if (nc < NCHUNK) {
                    const float* src = &cb[(size_t)(kw + nc*16 + kl)*Dd + ndc*32 + dh*16];
                    #pragma unroll
                    for (int i = 0; i < 4; i++) pre[i] = *(const float4*)&src[i*4];
                }
                const int db = dc*32;
                #pragma unroll 8
                for (int d = 0; d < 32; d++) {
                    ulonglong2 aA = *(const ulonglong2*)&ze[db + d][pg*8];
                    ulonglong2 aB = *(const ulonglong2*)&ze[db + d][pg*8 + 4];
                    float4 b = *(const float4*)&cbw[d*16 + cg*4];
                    MICRO_FMA2(acc2, aA, aB, b);
                }
            }
            // epilogue: scale by inverse norm, running argmax (ties -> lowest k)
            const float ivs[4] = {iv.x, iv.y, iv.z, iv.w};
            #pragma unroll
            for (int j = 0; j < 4; j++) {
                const int k = kc + cg*4 + j;
                const float s = ivs[j];
                #pragma unroll
                for (int i2 = 0; i2 < 4; i2++) {
                    float vlo = lo32f(acc2[i2][j]) * s;
                    float vhi = hi32f(acc2[i2][j]) * s;
                    if (vlo > best[i2*2])     { best[i2*2]     = vlo; bidx[i2*2]     = k; }
                    if (vhi > best[i2*2 + 1]) { best[i2*2 + 1] = vhi; bidx[i2*2 + 1] = k; }
                }
            }
        }

        // reduce over the 4 code-lanes of each quad (ties -> lowest k)
        #pragma unroll
        for (int i = 0; i < 8; i++) {
            float b = best[i]; int ix = bidx[i];
            #pragma unroll
            for (int m = 1; m < 4; m <<= 1) {
                float ob = __shfl_xor_sync(0xffffffffu, b, m);
                int   oi = __shfl_xor_sync(0xffffffffu, ix, m);
                if (ob > b || (ob == b && oi < ix)) { b = ob; ix = oi; }
            }
            if (cg == 0) { sbv[wid][pg*8 + i] = b; sbi[wid][pg*8 + i] = ix; }
        }
        __syncthreads();
        // fold the 4 warps (k-ordered: strict > keeps lowest k)
        if (tid < 64) {
            float bv = sbv[0][tid]; int bi = sbi[0][tid];
            #pragma unroll
            for (int w = 1; w < 4; w++) {
                float v = sbv[w][tid]; int i = sbi[w][tid];
                if (v > bv) { bv = v; bi = i; }
            }
            g_bestv[(size_t)slice*Pp + p0 + tid] = bv;
            g_besti[(size_t)slice*Pp + p0 + tid] = bi;
        }
    }
}

// ================= combine slices -> final index =================
__global__ void __launch_bounds__(256) combine_kernel(float* __restrict__ out)
{
    const int p = blockIdx.x * 256 + threadIdx.x;
    float bv = g_bestv[p];
    int   bi = g_besti[p];
    #pragma unroll
    for (int s = 1; s < NSLICE; s++) {
        float v = g_bestv[(size_t)s*Pp + p];
        int   i = g_besti[(size_t)s*Pp + p];
        if (v > bv) { bv = v; bi = i; }   // slices k-ordered: strict > keeps lowest k
    }
    g_idx[p] = bi;
    out[OUT_Y + p] = (float)bi;
}

// ================= VQ loss =================
__global__ void __launch_bounds__(128) loss_kernel(const float* __restrict__ cb)
{
    __shared__ float lred[4];
    const int tid = threadIdx.x;
    const int p0 = blockIdx.x * 64;
    float ls = 0.f;
    for (int i = tid; i < 64*256; i += 128) {
        int pos = i >> 8, d = i & 255;
        int ix = g_idx[p0 + pos];
        float diff = cb[(size_t)ix*Dd + d] - g_zet[(size_t)(p0 + pos)*Dd + d];
        ls = fmaf(diff, diff, ls);
    }
    #pragma unroll
    for (int m = 16; m; m >>= 1) ls += __shfl_xor_sync(0xffffffffu, ls, m);
    if ((tid & 31) == 0) lred[tid >> 5] = ls;
    __syncthreads();
    if (tid == 0) g_losspart[blockIdx.x] = lred[0] + lred[1] + lred[2] + lred[3];
}

// ================= y gather: y[n][c][l] = Wq[idx[n,l]][c] + out_b[c] =================
__global__ void __launch_bounds__(256) gather_kernel(
    const float* __restrict__ outb, float* __restrict__ out)
{
    extern __shared__ float sm[];   // [32][513]
    __shared__ int sidx[32];
    const int tid = threadIdx.x;
    const int l0 = blockIdx.x * 32, n = blockIdx.y;
    if (tid < 32) sidx[tid] = g_idx[n*Ll + l0 + tid];
    __syncthreads();
    for (int i = tid; i < 32*512; i += 256) {
        int l = i >> 9, c = i & 511;
        sm[l*513 + c] = g_Wq[(size_t)sidx[l]*Cc + c];
    }
    __syncthreads();
    for (int i = tid; i < 512*32; i += 256) {
        int c = i >> 5, l = i & 31;
        out[((size_t)n*Cc + c)*Ll + l0 + l] = sm[l*513 + c] + __ldg(&outb[c]);
    }
}

// ================= finalize losses =================
__global__ void finalize_kernel(float* __restrict__ out)
{
    const int tid = threadIdx.x;            // 128 threads: 4 warps, one per n
    const int n = tid >> 5, lane = tid & 31;
    float s = g_losspart[n*64 + lane] + g_losspart[n*64 + 32 + lane];
    #pragma unroll
    for (int m = 16; m; m >>= 1) s += __shfl_xor_sync(0xffffffffu, s, m);
    if (lane == 0) {
        float v = s * (1.0f / (float)(Dd * Ll));
        out[OUT_LOSS + n]     = v;   // cb_loss
        out[OUT_LOSS + 4 + n] = v;   // cm_loss (numerically identical)
    }
}

// ================= launch =================
extern "C" void kernel_launch(void* const* d_in, const int* in_sizes, int n_in,
                              void* d_out, int out_size)
{
    (void)in_sizes; (void)n_in; (void)out_size;
    const float* x    = (const float*)d_in[0];
    const float* vin  = (const float*)d_in[1];
    const float* gin  = (const float*)d_in[2];
    const float* bin  = (const float*)d_in[3];
    const float* vout = (const float*)d_in[4];
    const float* gout = (const float*)d_in[5];
    const float* bout = (const float*)d_in[6];
    const float* cb   = (const float*)d_in[7];
    float* out = (float*)d_out;

    const int SEARCH_SMEM = (256*64 + 4*32*16) * 4;   // 73728 B -> 3 blocks/SM
    const int GATHER_SMEM = 32*513*4;                 // 65664 B
    cudaFuncSetAttribute(search_kernel, cudaFuncAttributeMaxDynamicSharedMemorySize, SEARCH_SMEM);
    cudaFuncSetAttribute(search_kernel, cudaFuncAttributePreferredSharedMemoryCarveout, 100);
    cudaFuncSetAttribute(gather_kernel, cudaFuncAttributeMaxDynamicSharedMemorySize, GATHER_SMEM);

    prep_wn_kernel<<<Dd, 128>>>(vin, gin, Cc, 0);
    prep_wn_kernel<<<Cc, 128>>>(vout, gout, Dd, 1);
    prep_cbinv_kernel<<<Kk, 128>>>(cb);   // also resets g_work
    ze_gemm_kernel<<<dim3(Ll/64, Dd/64, Nn), 128>>>(x, bin);
    wq_gemm_kernel<<<dim3(Kk/64, Cc/64), 128>>>(cb);
    search_kernel<<<GRID_PERSIST, 128, SEARCH_SMEM>>>(cb);
    combine_kernel<<<Pp/256, 256>>>(out);
    loss_kernel<<<Pp/64, 128>>>(cb);
    gather_kernel<<<dim3(Ll/32, Nn), 256, GATHER_SMEM>>>(bout, out);
    finalize_kernel<<<1, 128>>>(out);
}

// round 11
// speedup vs baseline: 1.3849x; 1.0016x over previous
#include <cuda_runtime.h>
#include <math.h>

#define Nn 4
#define Cc 512
#define Ll 4096
#define Dd 256
#define Kk 8192
#define Pp (Nn*Ll)               // 16384 positions
#define OUT_Y ((size_t)Nn*Cc*Ll) // 8388608
#define OUT_LOSS (OUT_Y + Pp)    // 8404992

#define NSLICE 16                // k-slices per position tile (512 codes each)
#define NPT    (Pp/64)           // 256 position tiles
#define NITEMS (NPT*NSLICE)      // 4096 work items
#define SLICEK (Kk/NSLICE)       // 512 codes
#define WKCODES (SLICEK/4)       // 128 codes per warp per item
#define NCHUNK (WKCODES/16)      // 8 k-chunks of 16 codes per warp
#define GRID_PERSIST (152*3)     // 3 blocks/SM on GB300 (152 SMs)

typedef unsigned long long u64;

// packed fp32x2 FMA (sm_103a): 2 IEEE fp32 FMAs per instruction, bit-exact
#define FMA2(d, a, b, c) \
    asm("fma.rn.f32x2 %0, %1, %2, %3;" : "=l"(d) : "l"(a), "l"(b), "l"(c))
#define DUP2(d, s) \
    asm("mov.b64 %0, {%1, %1};" : "=l"(d) : "f"(s))

__device__ __forceinline__ float lo32f(u64 v) { return __uint_as_float((unsigned)(v & 0xffffffffu)); }
__device__ __forceinline__ float hi32f(u64 v) { return __uint_as_float((unsigned)(v >> 32)); }

// -------- device scratch (static, no allocation) --------
__device__ float g_Win[Dd*Cc];           // 512 KB
__device__ float g_Wout[Cc*Dd];          // 512 KB
__device__ float g_Wq[(size_t)Kk*Cc];    // 16 MB  (codebook @ W_out^T)
__device__ float g_invn[Kk];             // 1/max(||cb_k||, eps)
__device__ float g_zet[(size_t)Pp*Dd];   // 16 MB  z_e transposed: [pos][d]
__device__ int   g_idx[Pp];
__device__ float g_bestv[(size_t)NSLICE*Pp];  // per-slice best value
__device__ int   g_besti[(size_t)NSLICE*Pp];  // per-slice best index
__device__ float g_losspart[Pp/64];      // per-64-pos partial loss
__device__ int   g_work;                 // persistent work counter

// 16 packed FMAs for an 8(pos,paired)x4 microtile step
// NOTE: lo/hi lanes of each accumulator are two adjacent POSITIONS
// sharing the same code k (code operand is duplicated into both lanes).
#define MICRO_FMA2(acc2, aA, aB, b4)                                     \
    do {                                                                 \
        u64 bb0, bb1, bb2, bb3;                                          \
        DUP2(bb0, (b4).x); DUP2(bb1, (b4).y);                            \
        DUP2(bb2, (b4).z); DUP2(bb3, (b4).w);                            \
        FMA2(acc2[0][0], (aA).x, bb0, acc2[0][0]);                       \
        FMA2(acc2[0][1], (aA).x, bb1, acc2[0][1]);                       \
        FMA2(acc2[0][2], (aA).x, bb2, acc2[0][2]);                       \
        FMA2(acc2[0][3], (aA).x, bb3, acc2[0][3]);                       \
        FMA2(acc2[1][0], (aA).y, bb0, acc2[1][0]);                       \
        FMA2(acc2[1][1], (aA).y, bb1, acc2[1][1]);                       \
        FMA2(acc2[1][2], (aA).y, bb2, acc2[1][2]);                       \
        FMA2(acc2[1][3], (aA).y, bb3, acc2[1][3]);                       \
        FMA2(acc2[2][0], (aB).x, bb0, acc2[2][0]);                       \
        FMA2(acc2[2][1], (aB).x, bb1, acc2[2][1]);                       \
        FMA2(acc2[2][2], (aB).x, bb2, acc2[2][2]);                       \
        FMA2(acc2[2][3], (aB).x, bb3, acc2[2][3]);                       \
        FMA2(acc2[3][0], (aB).y, bb0, acc2[3][0]);                       \
        FMA2(acc2[3][1], (aB).y, bb1, acc2[3][1]);                       \
        FMA2(acc2[3][2], (aB).y, bb2, acc2[3][2]);                       \
        FMA2(acc2[3][3], (aB).y, bb3, acc2[3][3]);                       \
    } while (0)

// ================= prep: weight_norm rows =================
__global__ void __launch_bounds__(128) prep_wn_kernel(
    const float* __restrict__ v, const float* __restrict__ g, int cols, int sel)
{
    float* W = sel ? g_Wout : g_Win;
    const int r = blockIdx.x, tid = threadIdx.x;
    float s = 0.f;
    for (int c = tid; c < cols; c += 128) { float t = v[(size_t)r*cols + c]; s = fmaf(t, t, s); }
    #pragma unroll
    for (int m = 16; m; m >>= 1) s += __shfl_xor_sync(0xffffffffu, s, m);
    __shared__ float red[4];
    if ((tid & 31) == 0) red[tid >> 5] = s;
    __syncthreads();
    s = red[0] + red[1] + red[2] + red[3];
    const float scale = g[r] / sqrtf(s);
    for (int c = tid; c < cols; c += 128)
        W[(size_t)r*cols + c] = v[(size_t)r*cols + c] * scale;
}

// ================= prep: codebook inverse norms (+work counter reset) =================
__global__ void __launch_bounds__(128) prep_cbinv_kernel(const float* __restrict__ cb)
{
    const int r = blockIdx.x, tid = threadIdx.x;
    if (r == 0 && tid == 0) g_work = 0;
    float s = 0.f;
    for (int c = tid; c < Dd; c += 128) { float t = cb[(size_t)r*Dd + c]; s = fmaf(t, t, s); }
    #pragma unroll
    for (int m = 16; m; m >>= 1) s += __shfl_xor_sync(0xffffffffu, s, m);
    __shared__ float red[4];
    if ((tid & 31) == 0) red[tid >> 5] = s;
    __syncthreads();
    if (tid == 0) {
        s = red[0] + red[1] + red[2] + red[3];
        g_invn[r] = 1.f / fmaxf(sqrtf(s), 1e-8f);
    }
}

// ================= z_e GEMM: 64l x 64d tiles =================
__global__ void __launch_bounds__(128) ze_gemm_kernel(
    const float* __restrict__ x, const float* __restrict__ inb)
{
    __shared__ float xs[32][64];    // [c'][l']
    __shared__ float ws[32][68];    // [c'][d'] padded
    const int tid = threadIdx.x, ty = tid >> 4, tx = tid & 15;
    const int l0 = blockIdx.x * 64, d0 = blockIdx.y * 64, n = blockIdx.z;
    const float* xn = x + (size_t)n * Cc * Ll;
    u64 acc2[4][4];
    #pragma unroll
    for (int i = 0; i < 4; i++)
        #pragma unroll
        for (int j = 0; j < 4; j++) acc2[i][j] = 0ull;

    for (int c0 = 0; c0 < Cc; c0 += 32) {
        #pragma unroll
        for (int i = tid; i < 32*64; i += 128) { int c = i >> 6, l = i & 63; xs[c][l] = xn[(size_t)(c0 + c)*Ll + l0 + l]; }
        #pragma unroll
        for (int i = tid; i < 64*32; i += 128) { int d = i >> 5, c = i & 31; ws[c][d] = g_Win[(d0 + d)*Cc + c0 + c]; }
        __syncthreads();
        #pragma unroll 8
        for (int c = 0; c < 32; c++) {
            ulonglong2 aA = *(const ulonglong2*)&xs[c][ty*8];
            ulonglong2 aB = *(const ulonglong2*)&xs[c][ty*8 + 4];
            float4 b = *(const float4*)&ws[c][tx*4];
            MICRO_FMA2(acc2, aA, aB, b);
        }
        __syncthreads();
    }
    const float b0 = inb[d0 + tx*4 + 0], b1 = inb[d0 + tx*4 + 1];
    const float b2 = inb[d0 + tx*4 + 2], b3 = inb[d0 + tx*4 + 3];
    #pragma unroll
    for (int i2 = 0; i2 < 4; i2++) {
        #pragma unroll
        for (int h = 0; h < 2; h++) {
            int l = l0 + ty*8 + i2*2 + h;
            float4 o;
            o.x = (h ? hi32f(acc2[i2][0]) : lo32f(acc2[i2][0])) + b0;
            o.y = (h ? hi32f(acc2[i2][1]) : lo32f(acc2[i2][1])) + b1;
            o.z = (h ? hi32f(acc2[i2][2]) : lo32f(acc2[i2][2])) + b2;
            o.w = (h ? hi32f(acc2[i2][3]) : lo32f(acc2[i2][3])) + b3;
            *(float4*)&g_zet[((size_t)(n*Ll + l))*Dd + d0 + tx*4] = o;
        }
    }
}

// ================= Wq GEMM =================
__global__ void __launch_bounds__(128) wq_gemm_kernel(const float* __restrict__ cb)
{
    __shared__ float as_[32][68];   // [d'][k']
    __shared__ float bs_[32][68];   // [d'][c']
    const int tid = threadIdx.x, ty = tid >> 4, tx = tid & 15;
    const int k0 = blockIdx.x * 64, c0 = blockIdx.y * 64;
    u64 acc2[4][4];
    #pragma unroll
    for (int i = 0; i < 4; i++)
        #pragma unroll
        for (int j = 0; j < 4; j++) acc2[i][j] = 0ull;

    for (int d0 = 0; d0 < Dd; d0 += 32) {
        #pragma unroll
        for (int i = tid; i < 64*32; i += 128) { int k = i >> 5, d = i & 31; as_[d][k] = cb[(size_t)(k0 + k)*Dd + d0 + d]; }
        #pragma unroll
        for (int i = tid; i < 64*32; i += 128) { int c = i >> 5, d = i & 31; bs_[d][c] = g_Wout[(c0 + c)*Dd + d0 + d]; }
        __syncthreads();
        #pragma unroll 8
        for (int d = 0; d < 32; d++) {
            ulonglong2 aA = *(const ulonglong2*)&as_[d][ty*8];
            ulonglong2 aB = *(const ulonglong2*)&as_[d][ty*8 + 4];
            float4 b = *(const float4*)&bs_[d][tx*4];
            MICRO_FMA2(acc2, aA, aB, b);
        }
        __syncthreads();
    }
    #pragma unroll
    for (int i2 = 0; i2 < 4; i2++) {
        #pragma unroll
        for (int h = 0; h < 2; h++) {
            int k = k0 + ty*8 + i2*2 + h;
            float4 o;
            o.x = h ? hi32f(acc2[i2][0]) : lo32f(acc2[i2][0]);
            o.y = h ? hi32f(acc2[i2][1]) : lo32f(acc2[i2][1]);
            o.z = h ? hi32f(acc2[i2][2]) : lo32f(acc2[i2][2]);
            o.w = h ? hi32f(acc2[i2][3]) : lo32f(acc2[i2][3]);
            *(float4*)&g_Wq[(size_t)k*Cc + c0 + tx*4] = o;
        }
    }
}

// ================= persistent warp-autonomous split-K search =================
// Work item = (pos-tile of 64, k-slice of 512 codes). 4096 items pulled from a
// global counter by 456 persistent blocks (3/SM). Within an item each warp
// autonomously scans its own 128-code quarter using a warp-private smem
// staging buffer (no block-wide barriers in the mainloop).
__global__ void __launch_bounds__(128, 3) search_kernel(const float* __restrict__ cb)
{
    extern __shared__ float dynsm[];
    float (*ze)[64] = (float(*)[64])dynsm;   // [256 d][64 pos]  (65536 B)
    float* cbs = dynsm + 256*64;             // [4 warps][32 d][16 codes] (8192 B)
    __shared__ float sbv[4][64];
    __shared__ int   sbi[4][64];
    __shared__ int   s_item;

    const int tid = threadIdx.x;
    const int wid = tid >> 5, lane = tid & 31;
    const int pg = lane >> 2, cg = lane & 3;     // pos-group / code-group
    const int kl = lane >> 1, dh = lane & 1;     // staging load mapping
    float* cbw = cbs + wid * (32*16);            // this warp's private buffer

    int last_pt = -1;

    for (;;) {
        __syncthreads();   // previous item fully consumed before s_item/ze overwrite
        if (tid == 0) s_item = atomicAdd(&g_work, 1);
        __syncthreads();
        const int item = s_item;
        if (item >= NITEMS) break;
        const int pt = item >> 4;                // position tile (slices of a pt are consecutive)
        const int slice = item & (NSLICE-1);
        const int p0 = pt * 64;
        const int kw = slice*SLICEK + wid*WKCODES;   // this warp's code-range base

        if (pt != last_pt) {
            // conflict-free transposed load: warp covers 32 positions per d-quad
            #pragma unroll 4
            for (int it = 0; it < 32; it++) {
                int flat = it*128 + tid;
                int pos = flat & 63, d4 = flat >> 6;
                float4 v = *(const float4*)&g_zet[(size_t)(p0 + pos)*Dd + d4*4];
                ze[d4*4 + 0][pos] = v.x; ze[d4*4 + 1][pos] = v.y;
                ze[d4*4 + 2][pos] = v.z; ze[d4*4 + 3][pos] = v.w;
            }
            last_pt = pt;
            __syncthreads();   // publish ze to all warps
        }

        float best[8]; int bidx[8];
        #pragma unroll
        for (int i = 0; i < 8; i++) { best[i] = -3.4e38f; bidx[i] = 0; }

        // prefetch segment 0 (chunk 0, d-chunk 0): 16 codes x 32 d per warp
        float4 pre[4];
        {
            const float* src = &cb[(size_t)(kw + kl)*Dd + dh*16];
            #pragma unroll
            for (int i = 0; i < 4; i++) pre[i] = *(const float4*)&src[i*4];
        }

        for (int c = 0; c < NCHUNK; c++) {
            const int kc = kw + c*16;
            float4 iv = *(const float4*)&g_invn[kc + cg*4];
            u64 acc2[4][4];
            #pragma unroll
            for (int i = 0; i < 4; i++)
                #pragma unroll
                for (int j = 0; j < 4; j++) acc2[i][j] = 0ull;

            for (int dc = 0; dc < 8; dc++) {
                __syncwarp();   // prior segment's LDS of cbw done before overwrite
                // commit: cbw[d_local][k_local], d_local = dh*16 + i*4 + j
                #pragma unroll
                for (int i = 0; i < 4; i++) {
                    float* dst = &cbw[(dh*16 + i*4)*16 + kl];
                    dst[0]  = pre[i].x;
                    dst[16] = pre[i].y;
                    dst[32] = pre[i].z;
                    dst[48] = pre[i].w;
                }
                __syncwarp();
                // prefetch next segment (warp-local pipelining)
                int nc = c, ndc = dc + 1;
                if (ndc == 8) { ndc = 0; nc = c + 1; }
                if (nc < NCHUNK) {
                    const float* src = &cb[(size_t)(kw + nc*16 + kl)*Dd + ndc*32 + dh*16];
                    #pragma unroll
                    for (int i = 0; i < 4; i++) pre[i] = *(const float4*)&src[i*4];
                }
                const int db = dc*32;
                #pragma unroll 8
                for (int d = 0; d < 32; d++) {
                    ulonglong2 aA = *(const ulonglong2*)&ze[db + d][pg*8];
                    ulonglong2 aB = *(const ulonglong2*)&ze[db + d][pg*8 + 4];
                    float4 b = *(const float4*)&cbw[d*16 + cg*4];
                    MICRO_FMA2(acc2, aA, aB, b);
                }
            }
            // epilogue: scale by inverse norm, running argmax (ties -> lowest k)
            const float ivs[4] = {iv.x, iv.y, iv.z, iv.w};
            #pragma unroll
            for (int j = 0; j < 4; j++) {
                const int k = kc + cg*4 + j;
                const float s = ivs[j];
                #pragma unroll
                for (int i2 = 0; i2 < 4; i2++) {
                    float vlo = lo32f(acc2[i2][j]) * s;
                    float vhi = hi32f(acc2[i2][j]) * s;
                    if (vlo > best[i2*2])     { best[i2*2]     = vlo; bidx[i2*2]     = k; }
                    if (vhi > best[i2*2 + 1]) { best[i2*2 + 1] = vhi; bidx[i2*2 + 1] = k; }
                }
            }
        }

        // reduce over the 4 code-lanes of each quad (ties -> lowest k)
        #pragma unroll
        for (int i = 0; i < 8; i++) {
            float b = best[i]; int ix = bidx[i];
            #pragma unroll
            for (int m = 1; m < 4; m <<= 1) {
                float ob = __shfl_xor_sync(0xffffffffu, b, m);
                int   oi = __shfl_xor_sync(0xffffffffu, ix, m);
                if (ob > b || (ob == b && oi < ix)) { b = ob; ix = oi; }
            }
            if (cg == 0) { sbv[wid][pg*8 + i] = b; sbi[wid][pg*8 + i] = ix; }
        }
        __syncthreads();
        // fold the 4 warps (k-ordered: strict > keeps lowest k)
        if (tid < 64) {
            float bv = sbv[0][tid]; int bi = sbi[0][tid];
            #pragma unroll
            for (int w = 1; w < 4; w++) {
                float v = sbv[w][tid]; int i = sbi[w][tid];
                if (v > bv) { bv = v; bi = i; }
            }
            g_bestv[(size_t)slice*Pp + p0 + tid] = bv;
            g_besti[(size_t)slice*Pp + p0 + tid] = bi;
        }
    }
}

// ================= combine slices -> final index =================
__global__ void __launch_bounds__(256) combine_kernel(float* __restrict__ out)
{
    const int p = blockIdx.x * 256 + threadIdx.x;
    float bv = g_bestv[p];
    int   bi = g_besti[p];
    #pragma unroll
    for (int s = 1; s < NSLICE; s++) {
        float v = g_bestv[(size_t)s*Pp + p];
        int   i = g_besti[(size_t)s*Pp + p];
        if (v > bv) { bv = v; bi = i; }   // slices k-ordered: strict > keeps lowest k
    }
    g_idx[p] = bi;
    out[OUT_Y + p] = (float)bi;
}

// ================= VQ loss =================
__global__ void __launch_bounds__(128) loss_kernel(const float* __restrict__ cb)
{
    __shared__ float lred[4];
    const int tid = threadIdx.x;
    const int p0 = blockIdx.x * 64;
    float ls = 0.f;
    for (int i = tid; i < 64*256; i += 128) {
        int pos = i >> 8, d = i & 255;
        int ix = g_idx[p0 + pos];
        float diff = cb[(size_t)ix*Dd + d] - g_zet[(size_t)(p0 + pos)*Dd + d];
        ls = fmaf(diff, diff, ls);
    }
    #pragma unroll
    for (int m = 16; m; m >>= 1) ls += __shfl_xor_sync(0xffffffffu, ls, m);
    if ((tid & 31) == 0) lred[tid >> 5] = ls;
    __syncthreads();
    if (tid == 0) g_losspart[blockIdx.x] = lred[0] + lred[1] + lred[2] + lred[3];
}

// ================= y gather: y[n][c][l] = Wq[idx[n,l]][c] + out_b[c] =================
__global__ void __launch_bounds__(256) gather_kernel(
    const float* __restrict__ outb, float* __restrict__ out)
{
    extern __shared__ float sm[];   // [32][513]
    __shared__ int sidx[32];
    const int tid = threadIdx.x;
    const int l0 = blockIdx.x * 32, n = blockIdx.y;
    if (tid < 32) sidx[tid] = g_idx[n*Ll + l0 + tid];
    __syncthreads();
    for (int i = tid; i < 32*512; i += 256) {
        int l = i >> 9, c = i & 511;
        sm[l*513 + c] = g_Wq[(size_t)sidx[l]*Cc + c];
    }
    __syncthreads();
    for (int i = tid; i < 512*32; i += 256) {
        int c = i >> 5, l = i & 31;
        out[((size_t)n*Cc + c)*Ll + l0 + l] = sm[l*513 + c] + __ldg(&outb[c]);
    }
}

// ================= finalize losses =================
__global__ void finalize_kernel(float* __restrict__ out)
{
    const int tid = threadIdx.x;            // 128 threads: 4 warps, one per n
    const int n = tid >> 5, lane = tid & 31;
    float s = g_losspart[n*64 + lane] + g_losspart[n*64 + 32 + lane];
    #pragma unroll
    for (int m = 16; m; m >>= 1) s += __shfl_xor_sync(0xffffffffu, s, m);
    if (lane == 0) {
        float v = s * (1.0f / (float)(Dd * Ll));
        out[OUT_LOSS + n]     = v;   // cb_loss
        out[OUT_LOSS + 4 + n] = v;   // cm_loss (numerically identical)
    }
}

// ================= launch =================
extern "C" void kernel_launch(void* const* d_in, const int* in_sizes, int n_in,
                              void* d_out, int out_size)
{
    (void)in_sizes; (void)n_in; (void)out_size;
    const float* x    = (const float*)d_in[0];
    const float* vin  = (const float*)d_in[1];
    const float* gin  = (const float*)d_in[2];
    const float* bin  = (const float*)d_in[3];
    const float* vout = (const float*)d_in[4];
    const float* gout = (const float*)d_in[5];
    const float* bout = (const float*)d_in[6];
    const float* cb   = (const float*)d_in[7];
    float* out = (float*)d_out;

    const int SEARCH_SMEM = (256*64 + 4*32*16) * 4;   // 73728 B -> 3 blocks/SM
    const int GATHER_SMEM = 32*513*4;                 // 65664 B
    cudaFuncSetAttribute(search_kernel, cudaFuncAttributeMaxDynamicSharedMemorySize, SEARCH_SMEM);
    cudaFuncSetAttribute(search_kernel, cudaFuncAttributePreferredSharedMemoryCarveout, 100);
    cudaFuncSetAttribute(gather_kernel, cudaFuncAttributeMaxDynamicSharedMemorySize, GATHER_SMEM);

    prep_wn_kernel<<<Dd, 128>>>(vin, gin, Cc, 0);
    prep_wn_kernel<<<Cc, 128>>>(vout, gout, Dd, 1);
    prep_cbinv_kernel<<<Kk, 128>>>(cb);   // also resets g_work
    ze_gemm_kernel<<<dim3(Ll/64, Dd/64, Nn), 128>>>(x, bin);
    wq_gemm_kernel<<<dim3(Kk/64, Cc/64), 128>>>(cb);
    search_kernel<<<GRID_PERSIST, 128, SEARCH_SMEM>>>(cb);
    combine_kernel<<<Pp/256, 256>>>(out);
    loss_kernel<<<Pp/64, 128>>>(cb);
    gather_kernel<<<dim3(Ll/32, Nn), 256, GATHER_SMEM>>>(bout, out);
    finalize_kernel<<<1, 128>>>(out);
}

// round 13
// speedup vs baseline: 2.2445x; 1.6207x over previous
#include <cuda_runtime.h>
#include <cuda_bf16.h>
#include <math.h>
#include <stdint.h>

#define Nn 4
#define Cc 512
#define Ll 4096
#define Dd 256
#define Kk 8192
#define Pp (Nn*Ll)
#define OUT_Y ((size_t)Nn*Cc*Ll)
#define OUT_LOSS (OUT_Y + Pp)

typedef unsigned long long u64;
typedef unsigned int u32;

// ---- packed fp32x2 FMA (scalar GEMMs) ----
#define FMA2(d, a, b, c) asm("fma.rn.f32x2 %0, %1, %2, %3;" : "=l"(d) : "l"(a), "l"(b), "l"(c))
#define DUP2(d, s)       asm("mov.b64 %0, {%1, %1};" : "=l"(d) : "f"(s))
__device__ __forceinline__ float lo32f(u64 v){ return __uint_as_float((unsigned)(v & 0xffffffffu)); }
__device__ __forceinline__ float hi32f(u64 v){ return __uint_as_float((unsigned)(v >> 32)); }

// ---- mma.sync + cp.async (baseline sm_80+ PTX, OK for plain sm_103) ----
#define MMA_AB(d, A, B) \
    asm volatile("mma.sync.aligned.m16n8k16.row.col.f32.bf16.bf16.f32 " \
        "{%0,%1,%2,%3}, {%4,%5,%6,%7}, {%8,%9}, {%0,%1,%2,%3};" \
        : "+f"((d)[0]), "+f"((d)[1]), "+f"((d)[2]), "+f"((d)[3]) \
        : "r"((A).x), "r"((A).y), "r"((A).z), "r"((A).w), "r"((B).x), "r"((B).y))
#define MMA_Z(d, A, B) \
    asm volatile("mma.sync.aligned.m16n8k16.row.col.f32.bf16.bf16.f32 " \
        "{%0,%1,%2,%3}, {%4,%5,%6,%7}, {%8,%9}, {%10,%10,%10,%10};" \
        : "=f"((d)[0]), "=f"((d)[1]), "=f"((d)[2]), "=f"((d)[3]) \
        : "r"((A).x), "r"((A).y), "r"((A).z), "r"((A).w), "r"((B).x), "r"((B).y), "f"(0.0f))
#define CPA16(s, g) asm volatile("cp.async.cg.shared.global [%0], [%1], 16;" :: "r"(s), "l"(g) : "memory")
#define CPC()       asm volatile("cp.async.commit_group;" ::: "memory")
#define CPW(n)      asm volatile("cp.async.wait_group %0;" :: "n"(n) : "memory")

__device__ __forceinline__ uint32_t smem_u32(const void* p){
    uint32_t a; asm("{ .reg .u64 t; cvta.to.shared.u64 t, %1; cvt.u32.u64 %0, t; }" : "=r"(a) : "l"(p)); return a;
}
__device__ __forceinline__ u32 mono_enc(float f){
    u32 u = __float_as_uint(f);
    return (u & 0x80000000u) ? ~u : (u | 0x80000000u);
}
__device__ __forceinline__ float mono_dec(u32 e){
    return __uint_as_float((e & 0x80000000u) ? (e & 0x7FFFFFFFu) : ~e);
}

// -------- device scratch --------
__device__ float g_Win[Dd*Cc];
__device__ float g_Wout[Cc*Dd];
__device__ float g_Wq[(size_t)Kk*Cc];
__device__ float g_invn[Kk];
__device__ float g_zet[(size_t)Pp*Dd];
__device__ float g_anorm[Pp];
__device__ int   g_idx[Pp];
__device__ float g_losspart[Pp/64];
// fragment-ready bf16 operands (u32 = 2 bf16)
__device__ u32 g_Afr[(size_t)(Pp/16)*16*32*4];   // 2M u32: [rblk][t][lane][reg]
__device__ u32 g_Bfr[(size_t)(Kk/128)*16*16*32*2]; // 1M u32: [grp][t][j][lane][reg]

#define MICRO_FMA2(acc2, aA, aB, b4) do { \
        u64 bb0, bb1, bb2, bb3; \
        DUP2(bb0, (b4).x); DUP2(bb1, (b4).y); DUP2(bb2, (b4).z); DUP2(bb3, (b4).w); \
        FMA2(acc2[0][0], (aA).x, bb0, acc2[0][0]); FMA2(acc2[0][1], (aA).x, bb1, acc2[0][1]); \
        FMA2(acc2[0][2], (aA).x, bb2, acc2[0][2]); FMA2(acc2[0][3], (aA).x, bb3, acc2[0][3]); \
        FMA2(acc2[1][0], (aA).y, bb0, acc2[1][0]); FMA2(acc2[1][1], (aA).y, bb1, acc2[1][1]); \
        FMA2(acc2[1][2], (aA).y, bb2, acc2[1][2]); FMA2(acc2[1][3], (aA).y, bb3, acc2[1][3]); \
        FMA2(acc2[2][0], (aB).x, bb0, acc2[2][0]); FMA2(acc2[2][1], (aB).x, bb1, acc2[2][1]); \
        FMA2(acc2[2][2], (aB).x, bb2, acc2[2][2]); FMA2(acc2[2][3], (aB).x, bb3, acc2[2][3]); \
        FMA2(acc2[3][0], (aB).y, bb0, acc2[3][0]); FMA2(acc2[3][1], (aB).y, bb1, acc2[3][1]); \
        FMA2(acc2[3][2], (aB).y, bb2, acc2[3][2]); FMA2(acc2[3][3], (aB).y, bb3, acc2[3][3]); \
    } while (0)

// ================= prep =================
__global__ void __launch_bounds__(128) prep_wn_kernel(
    const float* __restrict__ v, const float* __restrict__ g, int cols, int sel)
{
    float* W = sel ? g_Wout : g_Win;
    const int r = blockIdx.x, tid = threadIdx.x;
    float s = 0.f;
    for (int c = tid; c < cols; c += 128) { float t = v[(size_t)r*cols + c]; s = fmaf(t, t, s); }
    #pragma unroll
    for (int m = 16; m; m >>= 1) s += __shfl_xor_sync(0xffffffffu, s, m);
    __shared__ float red[4];
    if ((tid & 31) == 0) red[tid >> 5] = s;
    __syncthreads();
    s = red[0] + red[1] + red[2] + red[3];
    const float scale = g[r] / sqrtf(s);
    for (int c = tid; c < cols; c += 128)
        W[(size_t)r*cols + c] = v[(size_t)r*cols + c] * scale;
}

__global__ void __launch_bounds__(128) prep_cbinv_kernel(const float* __restrict__ cb)
{
    const int r = blockIdx.x, tid = threadIdx.x;
    float s = 0.f;
    for (int c = tid; c < Dd; c += 128) { float t = cb[(size_t)r*Dd + c]; s = fmaf(t, t, s); }
    #pragma unroll
    for (int m = 16; m; m >>= 1) s += __shfl_xor_sync(0xffffffffu, s, m);
    __shared__ float red[4];
    if ((tid & 31) == 0) red[tid >> 5] = s;
    __syncthreads();
    if (tid == 0) {
        s = red[0] + red[1] + red[2] + red[3];
        g_invn[r] = 1.f / fmaxf(sqrtf(s), 1e-8f);
    }
}

// ================= z_e GEMM (fp32, exact) =================
__global__ void __launch_bounds__(128) ze_gemm_kernel(
    const float* __restrict__ x, const float* __restrict__ inb)
{
    __shared__ float xs[32][64];
    __shared__ float ws[32][68];
    const int tid = threadIdx.x, ty = tid >> 4, tx = tid & 15;
    const int l0 = blockIdx.x * 64, d0 = blockIdx.y * 64, n = blockIdx.z;
    const float* xn = x + (size_t)n * Cc * Ll;
    u64 acc2[4][4];
    #pragma unroll
    for (int i = 0; i < 4; i++) { acc2[i][0]=0; acc2[i][1]=0; acc2[i][2]=0; acc2[i][3]=0; }
    for (int c0 = 0; c0 < Cc; c0 += 32) {
        for (int i = tid; i < 32*64; i += 128) { int c = i >> 6, l = i & 63; xs[c][l] = xn[(size_t)(c0 + c)*Ll + l0 + l]; }
        for (int i = tid; i < 64*32; i += 128) { int d = i >> 5, c = i & 31; ws[c][d] = g_Win[(d0 + d)*Cc + c0 + c]; }
        __syncthreads();
        #pragma unroll 8
        for (int c = 0; c < 32; c++) {
            ulonglong2 aA = *(const ulonglong2*)&xs[c][ty*8];
            ulonglong2 aB = *(const ulonglong2*)&xs[c][ty*8 + 4];
            float4 b = *(const float4*)&ws[c][tx*4];
            MICRO_FMA2(acc2, aA, aB, b);
        }
        __syncthreads();
    }
    const float b0 = inb[d0+tx*4], b1 = inb[d0+tx*4+1], b2 = inb[d0+tx*4+2], b3 = inb[d0+tx*4+3];
    #pragma unroll
    for (int i2 = 0; i2 < 4; i2++)
        #pragma unroll
        for (int h = 0; h < 2; h++) {
            int l = l0 + ty*8 + i2*2 + h;
            float4 o;
            o.x = (h ? hi32f(acc2[i2][0]) : lo32f(acc2[i2][0])) + b0;
            o.y = (h ? hi32f(acc2[i2][1]) : lo32f(acc2[i2][1])) + b1;
            o.z = (h ? hi32f(acc2[i2][2]) : lo32f(acc2[i2][2])) + b2;
            o.w = (h ? hi32f(acc2[i2][3]) : lo32f(acc2[i2][3])) + b3;
            *(float4*)&g_zet[((size_t)(n*Ll + l))*Dd + d0 + tx*4] = o;
        }
}

// ================= Wq GEMM =================
__global__ void __launch_bounds__(128) wq_gemm_kernel(const float* __restrict__ cb)
{
    __shared__ float as_[32][68];
    __shared__ float bs_[32][68];
    const int tid = threadIdx.x, ty = tid >> 4, tx = tid & 15;
    const int k0 = blockIdx.x * 64, c0 = blockIdx.y * 64;
    u64 acc2[4][4];
    #pragma unroll
    for (int i = 0; i < 4; i++) { acc2[i][0]=0; acc2[i][1]=0; acc2[i][2]=0; acc2[i][3]=0; }
    for (int d0 = 0; d0 < Dd; d0 += 32) {
        for (int i = tid; i < 64*32; i += 128) { int k = i >> 5, d = i & 31; as_[d][k] = cb[(size_t)(k0 + k)*Dd + d0 + d]; }
        for (int i = tid; i < 64*32; i += 128) { int c = i >> 5, d = i & 31; bs_[d][c] = g_Wout[(c0 + c)*Dd + d0 + d]; }
        __syncthreads();
        #pragma unroll 8
        for (int d = 0; d < 32; d++) {
            ulonglong2 aA = *(const ulonglong2*)&as_[d][ty*8];
            ulonglong2 aB = *(const ulonglong2*)&as_[d][ty*8 + 4];
            float4 b = *(const float4*)&bs_[d][tx*4];
            MICRO_FMA2(acc2, aA, aB, b);
        }
        __syncthreads();
    }
    #pragma unroll
    for (int i2 = 0; i2 < 4; i2++)
        #pragma unroll
        for (int h = 0; h < 2; h++) {
            int k = k0 + ty*8 + i2*2 + h;
            float4 o;
            o.x = h ? hi32f(acc2[i2][0]) : lo32f(acc2[i2][0]);
            o.y = h ? hi32f(acc2[i2][1]) : lo32f(acc2[i2][1]);
            o.z = h ? hi32f(acc2[i2][2]) : lo32f(acc2[i2][2]);
            o.w = h ? hi32f(acc2[i2][3]) : lo32f(acc2[i2][3]);
            *(float4*)&g_Wq[(size_t)k*Cc + c0 + tx*4] = o;
        }
}

// ================= anorm =================
__global__ void __launch_bounds__(256) anorm_kernel()
{
    const int w = threadIdx.x >> 5, lane = threadIdx.x & 31;
    const int pos = blockIdx.x * 8 + w;
    const float4* r = (const float4*)(g_zet + (size_t)pos*Dd);
    float4 a = r[lane*2], b = r[lane*2 + 1];
    float s = a.x*a.x + a.y*a.y + a.z*a.z + a.w*a.w + b.x*b.x + b.y*b.y + b.z*b.z + b.w*b.w;
    #pragma unroll
    for (int m = 16; m; m >>= 1) s += __shfl_xor_sync(0xffffffffu, s, m);
    if (lane == 0) g_anorm[pos] = sqrtf(s);
}

// ================= fragment-layout bf16 conversions =================
// A frag m16k16 (row,kk): lane=(row&7)*4+((kk&7)>>1); reg=((kk>>3)<<1)|(row>>3); half=kk&1
__global__ void __launch_bounds__(256) split_ze_kernel()
{
    const size_t i = (size_t)blockIdx.x * 256 + threadIdx.x;
    const int pos = (int)(i >> 8), d = (int)(i & 255);
    const int r = pos >> 4, row = pos & 15, t = d >> 4, kk = d & 15;
    const int lane = (row & 7)*4 + ((kk & 7) >> 1);
    const int reg = ((kk >> 3) << 1) | (row >> 3);
    const size_t u32i = (((size_t)r*16 + t)*32 + lane)*4 + reg;
    ((__nv_bfloat16*)g_Afr)[u32i*2 + (kk & 1)] = __float2bfloat16(g_zet[i]);
}
// B frag k16n8 (n,kk): lane=n*4+((kk&7)>>1); reg=kk>>3; half=kk&1. Pre-scaled by invn.
__global__ void __launch_bounds__(256) split_cb_kernel(const float* __restrict__ cb)
{
    const size_t i = (size_t)blockIdx.x * 256 + threadIdx.x;
    const int k = (int)(i >> 8), d = (int)(i & 255);
    const int g = k >> 7, rowc = k & 127, j = rowc >> 3, n = rowc & 7;
    const int t = d >> 4, kk = d & 15;
    const int lane = n*4 + ((kk & 7) >> 1);
    const int reg = kk >> 3;
    const size_t u32i = (size_t)g*16384 + (((size_t)t*16 + j)*32 + lane)*2 + reg;
    ((__nv_bfloat16*)g_Bfr)[u32i*2 + (kk & 1)] = __float2bfloat16(cb[i] * g_invn[k]);
}

// ================= exact fp32 rescore =================
__device__ void rescore(int pos, int k, const float* __restrict__ cb, u64* slot)
{
    const float4* ar = (const float4*)(g_zet + (size_t)pos*Dd);
    const float4* br = (const float4*)(cb + (size_t)k*Dd);
    float s = 0.f;
    #pragma unroll 8
    for (int i = 0; i < 64; i++) {
        float4 a = ar[i], b = br[i];
        s = fmaf(a.x, b.x, s); s = fmaf(a.y, b.y, s);
        s = fmaf(a.z, b.z, s); s = fmaf(a.w, b.w, s);
    }
    float sim = s * __ldg(&g_invn[k]);
    u64 key = ((u64)mono_enc(sim) << 32) | (u64)(u32)(8191 - k);
    atomicMax(slot, key);
}

// ================= bf16 tensor-core screen + exact rescore =================
// CTA = 128 positions, 256 threads (8 warps: 4 pos-rowgroups x 2 code-colgroups).
// Pass A: max of bf16 sims per position. Pass B: candidates within rigorous
// error margin -> exact fp32 rescore -> packed atomicMax (value desc, k asc).
__global__ void __launch_bounds__(256, 1) mma_search_kernel(
    const float* __restrict__ cb, float* __restrict__ out)
{
    extern __shared__ unsigned char dsm[];   // [0,64K): A  [64K,128K): B0  [128K,192K): B1
    __shared__ u32 maxu[128];
    __shared__ u64 sb64[128];
    __shared__ float tfs[128];

    const int tid = threadIdx.x, w = tid >> 5, lane = tid & 31;
    const int rowgrp = w & 3, colgrp = w >> 2;
    const int p0 = blockIdx.x * 128;
    const uint32_t sbase = smem_u32(dsm);
    const uint4* sAv = (const uint4*)dsm;

    if (tid < 128) { maxu[tid] = 0u; sb64[tid] = 0ull; }

    // prime: A tile (64KB) + B group 0 (64KB), one commit group
    {
        const char* Asrc = (const char*)g_Afr + (size_t)(p0 >> 4) * 8192;
        const char* Bsrc = (const char*)g_Bfr;
        for (int it = 0; it < 16; it++) {
            int off = (it*256 + tid) * 16;
            CPA16(sbase + off, Asrc + off);
            CPA16(sbase + 65536 + off, Bsrc + off);
        }
        CPC();
    }

    int pps[4];
    #pragma unroll
    for (int mt = 0; mt < 2; mt++)
        #pragma unroll
        for (int eh = 0; eh < 2; eh++)
            pps[mt*2 + eh] = rowgrp*32 + mt*16 + (lane >> 2) + eh*8;

    float maxv[4] = {-3.4e38f, -3.4e38f, -3.4e38f, -3.4e38f};
    float tfr[4] = {0.f, 0.f, 0.f, 0.f};

    for (int pass = 0; pass < 2; pass++) {
        if (pass == 1) {
            __syncthreads();
            if (tid < 128) tfs[tid] = mono_dec(maxu[tid]) - 0.012f * g_anorm[p0 + tid];
            __syncthreads();
            #pragma unroll
            for (int s = 0; s < 4; s++) tfr[s] = tfs[pps[s]];
            // re-prime B group 0
            const char* Bsrc = (const char*)g_Bfr;
            for (int it = 0; it < 16; it++) {
                int off = (it*256 + tid) * 16;
                CPA16(sbase + 65536 + off, Bsrc + off);
            }
            CPC();
        }
        for (int g = 0; g < 64; g++) {
            __syncthreads();   // prior compute done before overwriting the other buf
            if (g < 63) {
                const char* src = (const char*)g_Bfr + (size_t)(g + 1) * 65536;
                uint32_t dst = sbase + 65536 + ((g + 1) & 1) * 65536;
                for (int it = 0; it < 16; it++) {
                    int off = (it*256 + tid) * 16;
                    CPA16(dst + off, src + off);
                }
                CPC();
                CPW(1);
            } else {
                CPW(0);
            }
            __syncthreads();

            const uint2* sBv = (const uint2*)(dsm + 65536 + (size_t)(g & 1) * 65536);
            float d0[8][4], d1[8][4];
            #pragma unroll
            for (int t = 0; t < 16; t++) {
                uint4 A0 = sAv[(rowgrp*32 + t)*32 + lane];
                uint4 A1 = sAv[(rowgrp*32 + 16 + t)*32 + lane];
                #pragma unroll
                for (int j = 0; j < 8; j++) {
                    uint2 B = sBv[(t*16 + colgrp*8 + j)*32 + lane];
                    if (t == 0) { MMA_Z(d0[j], A0, B); MMA_Z(d1[j], A1, B); }
                    else        { MMA_AB(d0[j], A0, B); MMA_AB(d1[j], A1, B); }
                }
            }

            // epilogue
            #pragma unroll
            for (int mt = 0; mt < 2; mt++) {
                float (*dd)[4] = mt ? d1 : d0;
                #pragma unroll
                for (int eh = 0; eh < 2; eh++) {
                    float m = fmaxf(dd[0][eh*2], dd[0][eh*2 + 1]);
                    #pragma unroll
                    for (int j = 1; j < 8; j++)
                        m = fmaxf(m, fmaxf(dd[j][eh*2], dd[j][eh*2 + 1]));
                    const int s = mt*2 + eh;
                    if (pass == 0) {
                        maxv[s] = fmaxf(maxv[s], m);
                    } else if (m >= tfr[s]) {
                        #pragma unroll
                        for (int j = 0; j < 8; j++)
                            #pragma unroll
                            for (int h = 0; h < 2; h++)
                                if (dd[j][eh*2 + h] >= tfr[s]) {
                                    int k = g*128 + colgrp*64 + j*8 + (lane & 3)*2 + h;
                                    rescore(p0 + pps[s], k, cb, &sb64[pps[s]]);
                                }
                    }
                }
            }
        }
        if (pass == 0) {
            #pragma unroll
            for (int s = 0; s < 4; s++) atomicMax(&maxu[pps[s]], mono_enc(maxv[s]));
        }
    }

    __syncthreads();
    if (tid < 128) {
        int k = 8191 - (int)(u32)(sb64[tid] & 0xFFFFFFFFull);
        g_idx[p0 + tid] = k;
        out[OUT_Y + p0 + tid] = (float)k;
    }
}

// ================= VQ loss =================
__global__ void __launch_bounds__(128) loss_kernel(const float* __restrict__ cb)
{
    __shared__ float lred[4];
    const int tid = threadIdx.x;
    const int p0 = blockIdx.x * 64;
    float ls = 0.f;
    for (int i = tid; i < 64*256; i += 128) {
        int pos = i >> 8, d = i & 255;
        int ix = g_idx[p0 + pos];
        float diff = cb[(size_t)ix*Dd + d] - g_zet[(size_t)(p0 + pos)*Dd + d];
        ls = fmaf(diff, diff, ls);
    }
    #pragma unroll
    for (int m = 16; m; m >>= 1) ls += __shfl_xor_sync(0xffffffffu, ls, m);
    if ((tid & 31) == 0) lred[tid >> 5] = ls;
    __syncthreads();
    if (tid == 0) g_losspart[blockIdx.x] = lred[0] + lred[1] + lred[2] + lred[3];
}

// ================= y gather =================
__global__ void __launch_bounds__(256) gather_kernel(
    const float* __restrict__ outb, float* __restrict__ out)
{
    extern __shared__ float sm[];
    __shared__ int sidx[32];
    const int tid = threadIdx.x;
    const int l0 = blockIdx.x * 32, n = blockIdx.y;
    if (tid < 32) sidx[tid] = g_idx[n*Ll + l0 + tid];
    __syncthreads();
    for (int i = tid; i < 32*512; i += 256) {
        int l = i >> 9, c = i & 511;
        sm[l*513 + c] = g_Wq[(size_t)sidx[l]*Cc + c];
    }
    __syncthreads();
    for (int i = tid; i < 512*32; i += 256) {
        int c = i >> 5, l = i & 31;
        out[((size_t)n*Cc + c)*Ll + l0 + l] = sm[l*513 + c] + __ldg(&outb[c]);
    }
}

// ================= finalize losses =================
__global__ void finalize_kernel(float* __restrict__ out)
{
    const int tid = threadIdx.x;
    const int n = tid >> 5, lane = tid & 31;
    float s = g_losspart[n*64 + lane] + g_losspart[n*64 + 32 + lane];
    #pragma unroll
    for (int m = 16; m; m >>= 1) s += __shfl_xor_sync(0xffffffffu, s, m);
    if (lane == 0) {
        float v = s * (1.0f / (float)(Dd * Ll));
        out[OUT_LOSS + n]     = v;
        out[OUT_LOSS + 4 + n] = v;
    }
}

// ================= launch =================
extern "C" void kernel_launch(void* const* d_in, const int* in_sizes, int n_in,
                              void* d_out, int out_size)
{
    (void)in_sizes; (void)n_in; (void)out_size;
    const float* x    = (const float*)d_in[0];
    const float* vin  = (const float*)d_in[1];
    const float* gin  = (const float*)d_in[2];
    const float* bin  = (const float*)d_in[3];
    const float* vout = (const float*)d_in[4];
    const float* gout = (const float*)d_in[5];
    const float* bout = (const float*)d_in[6];
    const float* cb   = (const float*)d_in[7];
    float* out = (float*)d_out;

    const int MMA_SMEM    = 196608;      // 64KB A + 2x64KB B
    const int GATHER_SMEM = 32*513*4;
    cudaFuncSetAttribute(mma_search_kernel, cudaFuncAttributeMaxDynamicSharedMemorySize, MMA_SMEM);
    cudaFuncSetAttribute(mma_search_kernel, cudaFuncAttributePreferredSharedMemoryCarveout, 100);
    cudaFuncSetAttribute(gather_kernel, cudaFuncAttributeMaxDynamicSharedMemorySize, GATHER_SMEM);

    prep_wn_kernel<<<Dd, 128>>>(vin, gin, Cc, 0);
    prep_wn_kernel<<<Cc, 128>>>(vout, gout, Dd, 1);
    prep_cbinv_kernel<<<Kk, 128>>>(cb);
    ze_gemm_kernel<<<dim3(Ll/64, Dd/64, Nn), 128>>>(x, bin);
    anorm_kernel<<<Pp/8, 256>>>();
    split_ze_kernel<<<(int)(((size_t)Pp*Dd)/256), 256>>>();
    split_cb_kernel<<<(int)(((size_t)Kk*Dd)/256), 256>>>(cb);
    wq_gemm_kernel<<<dim3(Kk/64, Cc/64), 128>>>(cb);
    mma_search_kernel<<<Pp/128, 256, MMA_SMEM>>>(cb, out);
    loss_kernel<<<Pp/64, 128>>>(cb);
    gather_kernel<<<dim3(Ll/32, Nn), 256, GATHER_SMEM>>>(bout, out);
    finalize_kernel<<<1, 128>>>(out);
}